// round 13
// baseline (speedup 1.0000x reference)
#include <cuda_runtime.h>
#include <math.h>

#define NN 1024           // N = N_ = 1024 training/test points
#define LLt 4             // l = 4 tasks
#define DD 8              // input dim
#define NB 128            // factorization block size
#define NSTEP 8           // NN / NB
#define LDZ 1040          // padded leading dim for Z (1025 used cols)
#define NRHS 1025         // 1024 Cx columns + 1 ytil column
#define UPAD 132          // smem tile row padding for gemm kernels

// ---------------- device scratch (static: no allocation allowed) ----------------
__device__ float g_Ctt[NN * NN];        // rbf(test_X, test_X)
__device__ float g_Lf[LLt][NN * NN];    // per-batch A_i = s_i*C + I -> L panels in-place
__device__ float g_Z[LLt][NN * LDZ];    // per-batch RHS [Cx | ytil_i] -> T_i = L_i^{-1}[Cx|u]
__device__ float g_W[LLt][NN * NN];     // W_i partial (K half 0)
__device__ float g_W2[LLt][NN * NN];    // W_i partial (K half 1)
__device__ float g_Fp[LLt][NN];         // per-batch T_i^T u_i
__device__ float g_invL[LLt][NB * NB];  // per-step inverse of diag block

struct Small {
    float s[LLt];          // eigenvalues of B'
    float G[LLt][LLt];     // G[i][q] = (U^T D^{-1/2} B)[i][q]
    float B[LLt][LLt];     // task_K
    float dn[LLt];         // exp(log_noise)
    float DU[LLt][LLt];    // DU[p][i] = dns[p]*U[p][i]
    float inv2ls2;         // 0.5 / ls^2
};
__device__ Small g_sm;

// ---------------- small setup: task matrix, 4x4 Jacobi eig ----------------
__global__ void small_setup(const float* __restrict__ log_noise,
                            const float* __restrict__ covar_factor,
                            const float* __restrict__ log_var,
                            const float* __restrict__ log_ls, int rank)
{
    if (threadIdx.x != 0 || blockIdx.x != 0) return;
    double dn[LLt], dns[LLt];
    for (int p = 0; p < LLt; p++) {
        dn[p]  = exp((double)log_noise[p]);
        dns[p] = exp(-0.5 * (double)log_noise[p]);
    }
    double B[LLt][LLt];
    for (int q = 0; q < LLt; q++)
        for (int r = 0; r < LLt; r++) {
            double s = 0.0;
            for (int k = 0; k < rank; k++)
                s += (double)covar_factor[q * rank + k] * (double)covar_factor[r * rank + k];
            if (q == r) s += exp((double)log_var[q]);
            B[q][r] = s;
        }
    double A[LLt][LLt], V[LLt][LLt];
    for (int q = 0; q < LLt; q++)
        for (int r = 0; r < LLt; r++) {
            A[q][r] = dns[q] * B[q][r] * dns[r];
            V[q][r] = (q == r) ? 1.0 : 0.0;
        }
    for (int sweep = 0; sweep < 40; sweep++) {
        for (int p = 0; p < LLt - 1; p++)
            for (int q = p + 1; q < LLt; q++) {
                double apq = A[p][q];
                if (fabs(apq) < 1e-300) continue;
                double theta = 0.5 * atan2(2.0 * apq, A[q][q] - A[p][p]);
                double c = cos(theta), s = sin(theta);
                for (int k = 0; k < LLt; k++) {
                    double akp = A[k][p], akq = A[k][q];
                    A[k][p] = c * akp - s * akq;
                    A[k][q] = s * akp + c * akq;
                }
                for (int k = 0; k < LLt; k++) {
                    double apk = A[p][k], aqk = A[q][k];
                    A[p][k] = c * apk - s * aqk;
                    A[q][k] = s * apk + c * aqk;
                }
                for (int k = 0; k < LLt; k++) {
                    double vkp = V[k][p], vkq = V[k][q];
                    V[k][p] = c * vkp - s * vkq;
                    V[k][q] = s * vkp + c * vkq;
                }
            }
    }
    for (int i = 0; i < LLt; i++) g_sm.s[i] = (float)A[i][i];
    for (int p = 0; p < LLt; p++)
        for (int i = 0; i < LLt; i++)
            g_sm.DU[p][i] = (float)(dns[p] * V[p][i]);
    for (int i = 0; i < LLt; i++)
        for (int q = 0; q < LLt; q++) {
            double s = 0.0;
            for (int p = 0; p < LLt; p++) s += V[p][i] * dns[p] * B[p][q];
            g_sm.G[i][q] = (float)s;
        }
    for (int q = 0; q < LLt; q++)
        for (int r = 0; r < LLt; r++) g_sm.B[q][r] = (float)B[q][r];
    for (int p = 0; p < LLt; p++) g_sm.dn[p] = (float)dn[p];
    g_sm.inv2ls2 = (float)(0.5 * exp(-2.0 * (double)log_ls[0]));
}

// ---------------- merged RBF: A_b, Z (Cx cols + ytil col), Ctt ----------------
__global__ void rbf_all(const float* __restrict__ X, const float* __restrict__ tX,
                        const float* __restrict__ Y)
{
    int idx = blockIdx.x * 256 + threadIdx.x;
    int i = idx >> 10, j = idx & 1023;
    float dAA = 0.f, dAx = 0.f, dtt = 0.f;
    #pragma unroll
    for (int d = 0; d < DD; d++) {
        float xi = X[i * DD + d], xj = X[j * DD + d];
        float ti = tX[i * DD + d], tj = tX[j * DD + d];
        float a = xi - xj; dAA += a * a;
        float b = xi - tj; dAx += b * b;
        float c = ti - tj; dtt += c * c;
    }
    float s2 = g_sm.inv2ls2;
    float vAA = expf(-dAA * s2);
    float vAx = expf(-dAx * s2);
    g_Ctt[idx] = expf(-dtt * s2);
    float diag = (i == j) ? 1.f : 0.f;
    long zoff = (long)i * LDZ + j;
    #pragma unroll
    for (int b = 0; b < LLt; b++) {
        g_Lf[b][idx] = g_sm.s[b] * vAA + diag;
        g_Z[b][zoff] = vAx;
    }
    if (idx < NN) {
        int n = idx;
        float y0 = Y[n * 4 + 0], y1 = Y[n * 4 + 1], y2 = Y[n * 4 + 2], y3 = Y[n * 4 + 3];
        #pragma unroll
        for (int b = 0; b < LLt; b++)
            g_Z[b][(long)n * LDZ + NN] = y0 * g_sm.DU[0][b] + y1 * g_sm.DU[1][b]
                                       + y2 * g_sm.DU[2][b] + y3 * g_sm.DU[3][b];
    }
}

// ---------------- P = A21 * inv32^T, then trailing -= P P^T. UR*16 = panel height ----
// sI is the 32x33 static inv32 buffer of the CURRENT panel.
template<int UR>
__device__ __forceinline__ void panel_and_update(float (*sA)[129], float (*sI)[33],
                                                 int o, int tr, int tc)
{
    float pacc[UR][2];
    #pragma unroll
    for (int u = 0; u < UR; u++) { pacc[u][0] = 0.f; pacc[u][1] = 0.f; }
    #pragma unroll
    for (int q = 0; q < 32; q++) {
        float b0 = sI[tc][q];
        float b1 = sI[tc + 16][q];
        #pragma unroll
        for (int u = 0; u < UR; u++) {
            float a = sA[o + 32 + tr + 16 * u][o + q];
            pacc[u][0] += a * b0;
            pacc[u][1] += a * b1;
        }
    }
    __syncthreads();
    #pragma unroll
    for (int u = 0; u < UR; u++) {
        sA[o + 32 + tr + 16 * u][o + tc]      = pacc[u][0];
        sA[o + 32 + tr + 16 * u][o + tc + 16] = pacc[u][1];
    }
    __syncthreads();
    float upd[UR][UR];
    #pragma unroll
    for (int u = 0; u < UR; u++)
        #pragma unroll
        for (int v = 0; v < UR; v++) upd[u][v] = 0.f;
    #pragma unroll
    for (int q = 0; q < 32; q++) {
        float av[UR], bv[UR];
        #pragma unroll
        for (int u = 0; u < UR; u++) av[u] = sA[o + 32 + tr + 16 * u][o + q];
        #pragma unroll
        for (int v = 0; v < UR; v++) bv[v] = sA[o + 32 + tc + 16 * v][o + q];
        #pragma unroll
        for (int u = 0; u < UR; u++)
            #pragma unroll
            for (int v = 0; v < UR; v++)
                upd[u][v] += av[u] * bv[v];
    }
    #pragma unroll
    for (int u = 0; u < UR; u++)
        #pragma unroll
        for (int v = 0; v < UR; v++)
            sA[o + 32 + tr + 16 * u][o + 32 + tc + 16 * v] -= upd[u][v];
}

// ---------------- diag step v5: 66KB smem (sA only); invL lives in gmem (L2) ---
// Standalone kernel; small footprint so it CO-RESIDES with ustep blocks.
__global__ void __launch_bounds__(256)
diag_step(int k)
{
    extern __shared__ float dsm[];
    float (*sA)[129] = (float(*)[129])dsm;     // 128x129 = 66048 B
    __shared__ float sX32[32][33];             // serial inv32 of current panel
    __shared__ float rds[32];                  // recip diag of current panel
    int b = blockIdx.x;
    int t = threadIdx.x;
    int lane = t & 31, warp = t >> 5;
    int tr = t >> 4, tc = t & 15;
    int off = k * NB;
    float* Lb = g_Lf[b];
    float* IL = g_invL[b];

    // zero invL (upper triangle must be 0 for consumers), load A_kk
    for (int i = t; i < NB * NB; i += 256) IL[i] = 0.f;
    #pragma unroll 4
    for (int i = 0; i < 64; i++) {
        int e = t + i * 256;
        int r = e >> 7, c = e & 127;
        sA[r][c] = Lb[(long)(off + r) * NN + off + c];
    }
    __syncthreads();

    for (int p = 0; p < 4; p++) {
        int o = p * 32;
        if (warp == 0) {
            // 32x32 Cholesky in registers (row per lane, shfl broadcasts)
            float r[32];
            #pragma unroll
            for (int kk = 0; kk < 32; kk++) r[kk] = sA[o + lane][o + kk];
            #pragma unroll
            for (int j = 0; j < 32; j++) {
                float dj = __shfl_sync(0xffffffffu, r[j], j);
                float invd = rsqrtf(dj);
                float Lj = r[j] * invd;
                sA[o + lane][o + j] = (lane >= j) ? Lj : 0.f;
                if (lane == j) rds[j] = invd;
                #pragma unroll
                for (int kk = j + 1; kk < 32; kk++) {
                    float Lkj = __shfl_sync(0xffffffffu, Lj, kk);
                    r[kk] -= Lj * Lkj;
                }
            }
            __syncwarp();
            // inv32: lane = column c, streamed through sX32 (same-thread RAW only)
            {
                int c = lane;
                #pragma unroll
                for (int j = 0; j < 32; j++) sX32[j][c] = 0.f;
                sX32[c][c] = rds[c];
                #pragma unroll
                for (int j = 1; j < 32; j++) {
                    float s0 = 0.f, s1 = 0.f;
                    #pragma unroll
                    for (int kk = 0; kk < j; kk++) {
                        float v = sA[o + j][o + kk] * sX32[kk][c];
                        if (kk & 1) s1 += v; else s0 += v;
                    }
                    if (j > c) sX32[j][c] = -(s0 + s1) * rds[j];
                }
                // publish this panel's inv32 block to gmem invL
                #pragma unroll
                for (int j = 0; j < 32; j++)
                    if (j >= c) IL[(o + j) * 128 + o + c] = sX32[j][c];
            }
            __syncwarp();
        }
        __syncthreads();
        if (p == 0)      panel_and_update<6>(sA, sX32, o, tr, tc);
        else if (p == 1) panel_and_update<4>(sA, sX32, o, tr, tc);
        else if (p == 2) panel_and_update<2>(sA, sX32, o, tr, tc);
        __syncthreads();
    }

    // level 32->64: for g=0,1: X21 = -X2 * (L21 * X1); scratch = sX32
    for (int g = 0; g < 2; g++) {
        int go = g * 64;
        for (int e = t; e < 1024; e += 256) {
            int i = e >> 5, j = e & 31;
            float s = 0.f;
            #pragma unroll
            for (int q = 0; q < 32; q++)
                s += sA[go + 32 + i][go + q] * IL[(go + q) * 128 + go + j];
            sX32[i][j] = s;
        }
        __syncthreads();
        for (int e = t; e < 1024; e += 256) {
            int i = e >> 5, j = e & 31;
            float s = 0.f;
            #pragma unroll
            for (int q = 0; q < 32; q++)
                s += IL[(go + 32 + i) * 128 + go + 32 + q] * sX32[q][j];
            IL[(go + 32 + i) * 128 + go + j] = -s;
        }
        __syncthreads();
    }

    // level 64->128: X21 = -XD2 * (LL21 * XD1); tmp in sA upper-right quadrant
    {
        float a4[4], b4[4];
        float acc4[4][4];
        #pragma unroll
        for (int u = 0; u < 4; u++)
            #pragma unroll
            for (int v = 0; v < 4; v++) acc4[u][v] = 0.f;
        for (int q = 0; q < 64; q++) {
            #pragma unroll
            for (int u = 0; u < 4; u++) a4[u] = sA[64 + tr * 4 + u][q];
            #pragma unroll
            for (int v = 0; v < 4; v++) b4[v] = IL[q * 128 + tc * 4 + v];
            #pragma unroll
            for (int u = 0; u < 4; u++)
                #pragma unroll
                for (int v = 0; v < 4; v++)
                    acc4[u][v] += a4[u] * b4[v];
        }
        __syncthreads();               // level 32->64 IL reads done before overwrite of sA UR
        #pragma unroll
        for (int u = 0; u < 4; u++)
            #pragma unroll
            for (int v = 0; v < 4; v++)
                sA[tr * 4 + u][64 + tc * 4 + v] = acc4[u][v];
        __syncthreads();
        float ac2[4][4];
        #pragma unroll
        for (int u = 0; u < 4; u++)
            #pragma unroll
            for (int v = 0; v < 4; v++) ac2[u][v] = 0.f;
        for (int q = 0; q < 64; q++) {
            #pragma unroll
            for (int u = 0; u < 4; u++) a4[u] = IL[(64 + tr * 4 + u) * 128 + 64 + q];
            #pragma unroll
            for (int v = 0; v < 4; v++) b4[v] = sA[q][64 + tc * 4 + v];
            #pragma unroll
            for (int u = 0; u < 4; u++)
                #pragma unroll
                for (int v = 0; v < 4; v++)
                    ac2[u][v] += a4[u] * b4[v];
        }
        __syncthreads();
        #pragma unroll
        for (int u = 0; u < 4; u++)
            #pragma unroll
            for (int v = 0; v < 4; v++)
                IL[(64 + tr * 4 + u) * 128 + tc * 4 + v] = -ac2[u][v];
    }
}

// ---------------- panel step as GEMM: L21 = A21 * invL^T ; z' = invL * Z_k -----
__global__ void __launch_bounds__(256, 2)
panel_gemm(int k)
{
    extern __shared__ float dsm[];
    float* As = dsm;                 // [2][16][UPAD]
    float* Bs = dsm + 2 * 16 * UPAD;
    int b = blockIdx.y;
    int mrem = NSTEP - 1 - k;
    int bi = blockIdx.x;
    bool isP = bi < mrem;            // panel tile vs Z tile
    int off = k * NB;
    float* Lb = g_Lf[b];
    float* Zb = g_Z[b];
    const float* IL = g_invL[b];
    int tid = threadIdx.x;
    int tr = tid >> 4, tc = tid & 15;
    int rowbase = off + NB + bi * 128;
    int zcolbase = (bi - mrem) * 128;

    float acc[8][8];
    #pragma unroll
    for (int u = 0; u < 8; u++)
        #pragma unroll
        for (int v = 0; v < 8; v++) acc[u][v] = 0.f;

    float ra[8], rb[8];
    #pragma unroll
    for (int i = 0; i < 8; i++) {
        int e = tid + i * 256;
        int kk = e & 15, m = e >> 4;
        if (isP) {
            ra[i] = Lb[(long)(rowbase + m) * NN + off + kk];
            rb[i] = IL[m * 128 + kk];
        } else {
            ra[i] = IL[m * 128 + kk];
            int kz = e >> 7, n = e & 127;
            int col = zcolbase + n;
            rb[i] = (col < NRHS) ? Zb[(long)(off + kz) * LDZ + col] : 0.f;
        }
    }
    #pragma unroll
    for (int i = 0; i < 8; i++) {
        int e = tid + i * 256;
        int kk = e & 15, m = e >> 4;
        As[kk * UPAD + m] = ra[i];
        if (isP) Bs[kk * UPAD + m] = rb[i];
        else { int kz = e >> 7, n = e & 127; Bs[kz * UPAD + n] = rb[i]; }
    }
    __syncthreads();

    for (int it = 0; it < 8; it++) {
        int p = it & 1;
        if (it + 1 < 8) {
            int k0 = (it + 1) * 16;
            #pragma unroll
            for (int i = 0; i < 8; i++) {
                int e = tid + i * 256;
                int kk = e & 15, m = e >> 4;
                if (isP) {
                    ra[i] = Lb[(long)(rowbase + m) * NN + off + k0 + kk];
                    rb[i] = IL[m * 128 + k0 + kk];
                } else {
                    ra[i] = IL[m * 128 + k0 + kk];
                    int kz = e >> 7, n = e & 127;
                    int col = zcolbase + n;
                    rb[i] = (col < NRHS) ? Zb[(long)(off + k0 + kz) * LDZ + col] : 0.f;
                }
            }
        }
        float* Ap = As + p * 16 * UPAD;
        float* Bp = Bs + p * 16 * UPAD;
        #pragma unroll
        for (int kk = 0; kk < 16; kk++) {
            float a[8], bb[8];
            *reinterpret_cast<float4*>(&a[0])  = *reinterpret_cast<float4*>(Ap + kk * UPAD + tr * 4);
            *reinterpret_cast<float4*>(&a[4])  = *reinterpret_cast<float4*>(Ap + kk * UPAD + 64 + tr * 4);
            *reinterpret_cast<float4*>(&bb[0]) = *reinterpret_cast<float4*>(Bp + kk * UPAD + tc * 4);
            *reinterpret_cast<float4*>(&bb[4]) = *reinterpret_cast<float4*>(Bp + kk * UPAD + 64 + tc * 4);
            #pragma unroll
            for (int u = 0; u < 8; u++)
                #pragma unroll
                for (int v = 0; v < 8; v++)
                    acc[u][v] += a[u] * bb[v];
        }
        if (it + 1 < 8) {
            int q = (it + 1) & 1;
            float* Aq = As + q * 16 * UPAD;
            float* Bq = Bs + q * 16 * UPAD;
            #pragma unroll
            for (int i = 0; i < 8; i++) {
                int e = tid + i * 256;
                int kk = e & 15, m = e >> 4;
                Aq[kk * UPAD + m] = ra[i];
                if (isP) Bq[kk * UPAD + m] = rb[i];
                else { int kz = e >> 7, n = e & 127; Bq[kz * UPAD + n] = rb[i]; }
            }
        }
        __syncthreads();
    }

    #pragma unroll
    for (int u = 0; u < 8; u++) {
        int row = ((u < 4) ? tr * 4 + u : 64 + tr * 4 + (u - 4));
        #pragma unroll
        for (int v = 0; v < 8; v++) {
            int n = ((v < 4) ? tc * 4 + v : 64 + tc * 4 + (v - 4));
            if (isP) {
                Lb[(long)(rowbase + row) * NN + off + n] = acc[u][v];
            } else {
                int col = zcolbase + n;
                if (col < NRHS)
                    Zb[(long)(off + row) * LDZ + col] = acc[u][v];
            }
        }
    }
}

// ---------------- merged trailing update (K=128, double-buffered) -------------
// mode 0: ONLY tile (0,0) (launch grid (1,1,LLt)); mode 1: all except tile (0,0).
__global__ void __launch_bounds__(256, 2)
ustep(int k, int mode)
{
    extern __shared__ float dsm[];
    float* As = dsm;
    float* Bs = dsm + 2 * 16 * UPAD;
    int b = blockIdx.z;
    int mrem = NSTEP - 1 - k;
    int mt = mrem;
    int bi = blockIdx.x, bj = blockIdx.y;
    bool isA = bj < mt;
    if (isA && bj > bi) return;
    if (mode == 1 && isA && bi == 0 && bj == 0) return;   // tile (0,0) done in mode-0 launch
    int rowoff = (k + 1) * NB;
    float* Lb = g_Lf[b];
    float* Zb = g_Z[b];
    int tid = threadIdx.x;
    int tr = tid >> 4, tc = tid & 15;
    int zcolbase = (bj - mt) * 128;

    float acc[8][8];
    #pragma unroll
    for (int u = 0; u < 8; u++)
        #pragma unroll
        for (int v = 0; v < 8; v++) acc[u][v] = 0.f;

    float ra[8], rb[8];
    const long arow = (long)(rowoff + bi * 128) * NN + k * NB;
    const long brow = isA ? (long)(rowoff + bj * 128) * NN + k * NB : 0;

    #pragma unroll
    for (int i = 0; i < 8; i++) {
        int e = tid + i * 256;
        int kk = e & 15, m = e >> 4;
        ra[i] = Lb[arow + (long)m * NN + kk];
        if (isA) rb[i] = Lb[brow + (long)m * NN + kk];
        else {
            int kz = e >> 7, n = e & 127;
            int col = zcolbase + n;
            rb[i] = (col < NRHS) ? Zb[(long)(k * NB + kz) * LDZ + col] : 0.f;
        }
    }
    #pragma unroll
    for (int i = 0; i < 8; i++) {
        int e = tid + i * 256;
        int kk = e & 15, m = e >> 4;
        As[kk * UPAD + m] = ra[i];
        if (isA) Bs[kk * UPAD + m] = rb[i];
        else { int kz = e >> 7, n = e & 127; Bs[kz * UPAD + n] = rb[i]; }
    }
    __syncthreads();

    for (int it = 0; it < 8; it++) {
        int p = it & 1;
        if (it + 1 < 8) {
            int k0 = (it + 1) * 16;
            #pragma unroll
            for (int i = 0; i < 8; i++) {
                int e = tid + i * 256;
                int kk = e & 15, m = e >> 4;
                ra[i] = Lb[arow + (long)m * NN + k0 + kk];
                if (isA) rb[i] = Lb[brow + (long)m * NN + k0 + kk];
                else {
                    int kz = e >> 7, n = e & 127;
                    int col = zcolbase + n;
                    rb[i] = (col < NRHS) ? Zb[(long)(k * NB + k0 + kz) * LDZ + col] : 0.f;
                }
            }
        }
        float* Ap = As + p * 16 * UPAD;
        float* Bp = Bs + p * 16 * UPAD;
        #pragma unroll
        for (int kk = 0; kk < 16; kk++) {
            float a[8], bb[8];
            *reinterpret_cast<float4*>(&a[0])  = *reinterpret_cast<float4*>(Ap + kk * UPAD + tr * 4);
            *reinterpret_cast<float4*>(&a[4])  = *reinterpret_cast<float4*>(Ap + kk * UPAD + 64 + tr * 4);
            *reinterpret_cast<float4*>(&bb[0]) = *reinterpret_cast<float4*>(Bp + kk * UPAD + tc * 4);
            *reinterpret_cast<float4*>(&bb[4]) = *reinterpret_cast<float4*>(Bp + kk * UPAD + 64 + tc * 4);
            #pragma unroll
            for (int u = 0; u < 8; u++)
                #pragma unroll
                for (int v = 0; v < 8; v++)
                    acc[u][v] += a[u] * bb[v];
        }
        if (it + 1 < 8) {
            int q = (it + 1) & 1;
            float* Aq = As + q * 16 * UPAD;
            float* Bq = Bs + q * 16 * UPAD;
            #pragma unroll
            for (int i = 0; i < 8; i++) {
                int e = tid + i * 256;
                int kk = e & 15, m = e >> 4;
                Aq[kk * UPAD + m] = ra[i];
                if (isA) Bq[kk * UPAD + m] = rb[i];
                else { int kz = e >> 7, n = e & 127; Bq[kz * UPAD + n] = rb[i]; }
            }
        }
        __syncthreads();
    }

    #pragma unroll
    for (int u = 0; u < 8; u++) {
        int row = bi * 128 + ((u < 4) ? tr * 4 + u : 64 + tr * 4 + (u - 4));
        #pragma unroll
        for (int v = 0; v < 8; v++) {
            int n = ((v < 4) ? tc * 4 + v : 64 + tc * 4 + (v - 4));
            if (isA) {
                int col = bj * 128 + n;
                Lb[(long)(rowoff + row) * NN + rowoff + col] -= acc[u][v];
            } else {
                int col = zcolbase + n;
                if (col < NRHS)
                    Zb[(long)(rowoff + row) * LDZ + col] -= acc[u][v];
            }
        }
    }
}

// ---------------- W = T^T T (batched syrk, K-split x2, lower + mirror) --------
__global__ void __launch_bounds__(256, 2)
syrk_W()
{
    extern __shared__ float dsm[];
    float* As = dsm;
    float* Bs = dsm + 2 * 16 * UPAD;
    int bi = blockIdx.x, bj = blockIdx.y;
    int zz = blockIdx.z;
    int b = zz & 3, half = zz >> 2;
    if (bj > bi) return;
    const float* Zb = g_Z[b];
    float* Wb = half ? g_W2[b] : g_W[b];
    int kbase = half * 32;
    int tid = threadIdx.x;
    int tr = tid >> 4, tc = tid & 15;
    float acc[8][8];
    #pragma unroll
    for (int u = 0; u < 8; u++)
        #pragma unroll
        for (int v = 0; v < 8; v++) acc[u][v] = 0.f;

    float ra[8], rb[8];
    #pragma unroll
    for (int i = 0; i < 8; i++) {
        int e = tid + i * 256;
        int kk = e & 15, m = e >> 4;
        ra[i] = Zb[(long)(kbase * 16 + kk) * LDZ + bi * 128 + m];
        rb[i] = Zb[(long)(kbase * 16 + kk) * LDZ + bj * 128 + m];
    }
    #pragma unroll
    for (int i = 0; i < 8; i++) {
        int e = tid + i * 256;
        int kk = e & 15, m = e >> 4;
        As[kk * UPAD + m] = ra[i];
        Bs[kk * UPAD + m] = rb[i];
    }
    __syncthreads();

    for (int it = 0; it < 32; it++) {
        int p = it & 1;
        if (it + 1 < 32) {
            int k0 = (kbase + it + 1) * 16;
            #pragma unroll
            for (int i = 0; i < 8; i++) {
                int e = tid + i * 256;
                int kk = e & 15, m = e >> 4;
                ra[i] = Zb[(long)(k0 + kk) * LDZ + bi * 128 + m];
                rb[i] = Zb[(long)(k0 + kk) * LDZ + bj * 128 + m];
            }
        }
        float* Ap = As + p * 16 * UPAD;
        float* Bp = Bs + p * 16 * UPAD;
        #pragma unroll
        for (int kk = 0; kk < 16; kk++) {
            float a[8], bb[8];
            *reinterpret_cast<float4*>(&a[0])  = *reinterpret_cast<float4*>(Ap + kk * UPAD + tr * 4);
            *reinterpret_cast<float4*>(&a[4])  = *reinterpret_cast<float4*>(Ap + kk * UPAD + 64 + tr * 4);
            *reinterpret_cast<float4*>(&bb[0]) = *reinterpret_cast<float4*>(Bp + kk * UPAD + tc * 4);
            *reinterpret_cast<float4*>(&bb[4]) = *reinterpret_cast<float4*>(Bp + kk * UPAD + 64 + tc * 4);
            #pragma unroll
            for (int u = 0; u < 8; u++)
                #pragma unroll
                for (int v = 0; v < 8; v++)
                    acc[u][v] += a[u] * bb[v];
        }
        if (it + 1 < 32) {
            int q = (it + 1) & 1;
            float* Aq = As + q * 16 * UPAD;
            float* Bq = Bs + q * 16 * UPAD;
            #pragma unroll
            for (int i = 0; i < 8; i++) {
                int e = tid + i * 256;
                int kk = e & 15, m = e >> 4;
                Aq[kk * UPAD + m] = ra[i];
                Bq[kk * UPAD + m] = rb[i];
            }
        }
        __syncthreads();
    }

    #pragma unroll
    for (int u = 0; u < 8; u++) {
        int row = bi * 128 + ((u < 4) ? tr * 4 + u : 64 + tr * 4 + (u - 4));
        #pragma unroll
        for (int v = 0; v < 8; v++) {
            int col = bj * 128 + ((v < 4) ? tc * 4 + v : 64 + tc * 4 + (v - 4));
            float o = acc[u][v];
            Wb[(long)row * NN + col] = o;
            if (bi != bj) Wb[(long)col * NN + row] = o;
        }
    }
}

// ---------------- fmean: Fp_b[m] = sum_n T_b[n][m] * u_b[n] ----------------
__global__ void fmean_dot()
{
    int b = blockIdx.y;
    int m = blockIdx.x * 256 + threadIdx.x;
    __shared__ float su[NN];
    const float* Zb = g_Z[b];
    for (int n = threadIdx.x; n < NN; n += 256) su[n] = Zb[(long)n * LDZ + NN];
    __syncthreads();
    float a0 = 0.f, a1 = 0.f, a2 = 0.f, a3 = 0.f;
    #pragma unroll 4
    for (int n = 0; n < NN; n += 4) {
        a0 += Zb[(long)n * LDZ + m]       * su[n];
        a1 += Zb[(long)(n + 1) * LDZ + m] * su[n + 1];
        a2 += Zb[(long)(n + 2) * LDZ + m] * su[n + 2];
        a3 += Zb[(long)(n + 3) * LDZ + m] * su[n + 3];
    }
    g_Fp[b][m] = (a0 + a1) + (a2 + a3);
}

__global__ void fmean_comb(float* __restrict__ out)
{
    int m = blockIdx.x * 256 + threadIdx.x;
    if (m >= NN) return;
    float f0 = g_Fp[0][m], f1 = g_Fp[1][m], f2 = g_Fp[2][m], f3 = g_Fp[3][m];
    #pragma unroll
    for (int q = 0; q < LLt; q++) {
        float v = f0 * g_sm.G[0][q] + f1 * g_sm.G[1][q]
                + f2 * g_sm.G[2][q] + f3 * g_sm.G[3][q];
        out[(long)q * NN + m] = v;
        out[4096L + 2L * 16777216L + (long)m * 4 + q] = v;
    }
}

// ---------------- fvar assembly (sums the two K-half W partials) --------------
__global__ void fvar_kernel(float* __restrict__ out)
{
    int idx = blockIdx.x * 256 + threadIdx.x;
    int a  = idx >> 8;
    int b4 = idx & 255;
    long vi = (long)a * 256 + b4;
    float4 vt = reinterpret_cast<const float4*>(g_Ctt)[vi];
    float4 w0 = reinterpret_cast<const float4*>(g_W[0])[vi];
    float4 w1 = reinterpret_cast<const float4*>(g_W[1])[vi];
    float4 w2 = reinterpret_cast<const float4*>(g_W[2])[vi];
    float4 w3 = reinterpret_cast<const float4*>(g_W[3])[vi];
    float4 x0 = reinterpret_cast<const float4*>(g_W2[0])[vi];
    float4 x1 = reinterpret_cast<const float4*>(g_W2[1])[vi];
    float4 x2 = reinterpret_cast<const float4*>(g_W2[2])[vi];
    float4 x3 = reinterpret_cast<const float4*>(g_W2[3])[vi];
    w0.x += x0.x; w0.y += x0.y; w0.z += x0.z; w0.w += x0.w;
    w1.x += x1.x; w1.y += x1.y; w1.z += x1.z; w1.w += x1.w;
    w2.x += x2.x; w2.y += x2.y; w2.z += x2.z; w2.w += x2.w;
    w3.x += x3.x; w3.y += x3.y; w3.z += x3.z; w3.w += x3.w;
    float4* fv = reinterpret_cast<float4*>(out + 4096);
    #pragma unroll
    for (int q = 0; q < 4; q++) {
        #pragma unroll
        for (int r = 0; r < 4; r++) {
            float cb = g_sm.B[q][r];
            float c0 = g_sm.G[0][q] * g_sm.G[0][r];
            float c1 = g_sm.G[1][q] * g_sm.G[1][r];
            float c2 = g_sm.G[2][q] * g_sm.G[2][r];
            float c3 = g_sm.G[3][q] * g_sm.G[3][r];
            float4 v;
            v.x = cb * vt.x - c0 * w0.x - c1 * w1.x - c2 * w2.x - c3 * w3.x;
            v.y = cb * vt.y - c0 * w0.y - c1 * w1.y - c2 * w2.y - c3 * w3.y;
            v.z = cb * vt.z - c0 * w0.z - c1 * w1.z - c2 * w2.z - c3 * w3.z;
            v.w = cb * vt.w - c0 * w0.w - c1 * w1.w - c2 * w2.w - c3 * w3.w;
            fv[(long)(q * NN + a) * 1024 + r * 256 + b4] = v;
        }
    }
}

// ---------------- noise output (zeros + diagonal in one pass) ----------------
__global__ void noise_fill(float* __restrict__ out)
{
    long i = (long)blockIdx.x * 256 + threadIdx.x;
    long base = i * 4;
    int row = (int)(base >> 12);
    int col0 = (int)(base & 4095);
    float4 v = make_float4(0.f, 0.f, 0.f, 0.f);
    if (row >= col0 && row < col0 + 4)
        reinterpret_cast<float*>(&v)[row - col0] = g_sm.dn[row >> 10];
    reinterpret_cast<float4*>(out + 4096 + 16777216L)[i] = v;
}

// ---------------- launcher (multi-stream graph: diag(k+1) || ustep_rest(k)) ----
extern "C" void kernel_launch(void* const* d_in, const int* in_sizes, int n_in,
                              void* d_out, int out_size)
{
    const float* X      = (const float*)d_in[0];
    const float* tX     = (const float*)d_in[1];
    const float* Y      = (const float*)d_in[2];
    const float* lnoise = (const float*)d_in[3];
    const float* cf     = (const float*)d_in[4];
    const float* lvar   = (const float*)d_in[5];
    const float* lls    = (const float*)d_in[6];
    float* out = (float*)d_out;
    int l = in_sizes[3];
    int rank = in_sizes[4] / l;
    (void)l;

    const int DSMEM = 128 * 129 * 4;                         // 66048 B (co-residency-sized)
    const int GSMEM = 2 * 2 * 16 * UPAD * 4;                 // 67584 B
    cudaFuncSetAttribute(diag_step,  cudaFuncAttributeMaxDynamicSharedMemorySize, DSMEM);
    cudaFuncSetAttribute(panel_gemm, cudaFuncAttributeMaxDynamicSharedMemorySize, GSMEM);
    cudaFuncSetAttribute(ustep,      cudaFuncAttributeMaxDynamicSharedMemorySize, GSMEM);
    cudaFuncSetAttribute(syrk_W,     cudaFuncAttributeMaxDynamicSharedMemorySize, GSMEM);

    int loPri, hiPri;
    cudaDeviceGetStreamPriorityRange(&loPri, &hiPri);
    cudaStream_t s2;
    cudaStreamCreateWithPriority(&s2, cudaStreamNonBlocking, hiPri);
    cudaEvent_t evA, evB;
    cudaEventCreateWithFlags(&evA, cudaEventDisableTiming);
    cudaEventCreateWithFlags(&evB, cudaEventDisableTiming);

    small_setup<<<1, 32>>>(lnoise, cf, lvar, lls, rank);
    rbf_all<<<NN * NN / 256, 256>>>(X, tX, Y);
    noise_fill<<<16384, 256>>>(out);
    diag_step<<<LLt, 256, DSMEM>>>(0);

    // factor + forward-solve sweep; diag(k+1) overlapped with ustep_rest(k) on s2
    for (int k = 0; k < NSTEP; k++) {
        int mrem = NSTEP - 1 - k;
        panel_gemm<<<dim3(mrem + 9, LLt), 256, GSMEM>>>(k);
        if (mrem > 0) {
            ustep<<<dim3(1, 1, LLt), 256, GSMEM>>>(k, 0);            // tile (0,0) only
            cudaEventRecord(evA, 0);
            cudaStreamWaitEvent(s2, evA, 0);
            diag_step<<<LLt, 256, DSMEM, s2>>>(k + 1);               // overlapped (co-resident)
            cudaEventRecord(evB, s2);
            ustep<<<dim3(mrem, mrem + 9, LLt), 256, GSMEM>>>(k, 1);  // rest of tiles
            cudaStreamWaitEvent(0, evB, 0);
        }
    }

    // W_i = T_i^T T_i  (batched syrk, K-split x2: 288 working CTAs)
    syrk_W<<<dim3(8, 8, LLt * 2), 256, GSMEM>>>();

    // fmean = sum_i G[i][q] * T_i^T u_i
    fmean_dot<<<dim3(4, LLt), 256>>>();
    fmean_comb<<<4, 256>>>(out);

    // fvar and noise outputs
    fvar_kernel<<<1024, 256>>>(out);
}

// round 14
// speedup vs baseline: 1.1601x; 1.1601x over previous
#include <cuda_runtime.h>
#include <math.h>

#define NN 1024           // N = N_ = 1024 training/test points
#define LLt 4             // l = 4 tasks
#define DD 8              // input dim
#define NB 128            // factorization block size
#define NSTEP 8           // NN / NB
#define LDZ 1152          // padded leading dim for Z (9 full 128-col tiles)
#define NRHS 1025         // 1024 Cx columns + 1 ytil column
#define UPAD 132          // smem tile row padding for gemm kernels

// ---------------- device scratch (static: no allocation allowed) ----------------
__device__ float g_Ctt[NN * NN];        // rbf(test_X, test_X)
__device__ float g_Lf[LLt][NN * NN];    // per-batch A_i = s_i*C + I -> L panels in-place
__device__ float g_Z[LLt][NN * LDZ];    // per-batch RHS [Cx | ytil_i]; cols >= NRHS stay 0
__device__ float g_W[LLt][NN * NN];     // W_i partial (K half 0)
__device__ float g_W2[LLt][NN * NN];    // W_i partial (K half 1)
__device__ float g_Fp[LLt][NN];         // per-batch T_i^T u_i
__device__ float g_invL[LLt][NB * NB];  // per-step inverse of diag block

struct Small {
    float s[LLt];          // eigenvalues of B'
    float G[LLt][LLt];     // G[i][q] = (U^T D^{-1/2} B)[i][q]
    float B[LLt][LLt];     // task_K
    float dn[LLt];         // exp(log_noise)
    float DU[LLt][LLt];    // DU[p][i] = dns[p]*U[p][i]
    float inv2ls2;         // 0.5 / ls^2
};
__device__ Small g_sm;

// ---------------- small setup: task matrix, 4x4 Jacobi eig ----------------
__global__ void small_setup(const float* __restrict__ log_noise,
                            const float* __restrict__ covar_factor,
                            const float* __restrict__ log_var,
                            const float* __restrict__ log_ls, int rank)
{
    if (threadIdx.x != 0 || blockIdx.x != 0) return;
    double dn[LLt], dns[LLt];
    for (int p = 0; p < LLt; p++) {
        dn[p]  = exp((double)log_noise[p]);
        dns[p] = exp(-0.5 * (double)log_noise[p]);
    }
    double B[LLt][LLt];
    for (int q = 0; q < LLt; q++)
        for (int r = 0; r < LLt; r++) {
            double s = 0.0;
            for (int k = 0; k < rank; k++)
                s += (double)covar_factor[q * rank + k] * (double)covar_factor[r * rank + k];
            if (q == r) s += exp((double)log_var[q]);
            B[q][r] = s;
        }
    double A[LLt][LLt], V[LLt][LLt];
    for (int q = 0; q < LLt; q++)
        for (int r = 0; r < LLt; r++) {
            A[q][r] = dns[q] * B[q][r] * dns[r];
            V[q][r] = (q == r) ? 1.0 : 0.0;
        }
    for (int sweep = 0; sweep < 40; sweep++) {
        for (int p = 0; p < LLt - 1; p++)
            for (int q = p + 1; q < LLt; q++) {
                double apq = A[p][q];
                if (fabs(apq) < 1e-300) continue;
                double theta = 0.5 * atan2(2.0 * apq, A[q][q] - A[p][p]);
                double c = cos(theta), s = sin(theta);
                for (int k = 0; k < LLt; k++) {
                    double akp = A[k][p], akq = A[k][q];
                    A[k][p] = c * akp - s * akq;
                    A[k][q] = s * akp + c * akq;
                }
                for (int k = 0; k < LLt; k++) {
                    double apk = A[p][k], aqk = A[q][k];
                    A[p][k] = c * apk - s * aqk;
                    A[q][k] = s * apk + c * aqk;
                }
                for (int k = 0; k < LLt; k++) {
                    double vkp = V[k][p], vkq = V[k][q];
                    V[k][p] = c * vkp - s * vkq;
                    V[k][q] = s * vkp + c * vkq;
                }
            }
    }
    for (int i = 0; i < LLt; i++) g_sm.s[i] = (float)A[i][i];
    for (int p = 0; p < LLt; p++)
        for (int i = 0; i < LLt; i++)
            g_sm.DU[p][i] = (float)(dns[p] * V[p][i]);
    for (int i = 0; i < LLt; i++)
        for (int q = 0; q < LLt; q++) {
            double s = 0.0;
            for (int p = 0; p < LLt; p++) s += V[p][i] * dns[p] * B[p][q];
            g_sm.G[i][q] = (float)s;
        }
    for (int q = 0; q < LLt; q++)
        for (int r = 0; r < LLt; r++) g_sm.B[q][r] = (float)B[q][r];
    for (int p = 0; p < LLt; p++) g_sm.dn[p] = (float)dn[p];
    g_sm.inv2ls2 = (float)(0.5 * exp(-2.0 * (double)log_ls[0]));
}

// ---------------- merged RBF: A_b, Z (Cx cols + ytil col), Ctt ----------------
__global__ void rbf_all(const float* __restrict__ X, const float* __restrict__ tX,
                        const float* __restrict__ Y)
{
    int idx = blockIdx.x * 256 + threadIdx.x;
    int i = idx >> 10, j = idx & 1023;
    float dAA = 0.f, dAx = 0.f, dtt = 0.f;
    #pragma unroll
    for (int d = 0; d < DD; d++) {
        float xi = X[i * DD + d], xj = X[j * DD + d];
        float ti = tX[i * DD + d], tj = tX[j * DD + d];
        float a = xi - xj; dAA += a * a;
        float b = xi - tj; dAx += b * b;
        float c = ti - tj; dtt += c * c;
    }
    float s2 = g_sm.inv2ls2;
    float vAA = expf(-dAA * s2);
    float vAx = expf(-dAx * s2);
    g_Ctt[idx] = expf(-dtt * s2);
    float diag = (i == j) ? 1.f : 0.f;
    long zoff = (long)i * LDZ + j;
    #pragma unroll
    for (int b = 0; b < LLt; b++) {
        g_Lf[b][idx] = g_sm.s[b] * vAA + diag;
        g_Z[b][zoff] = vAx;
    }
    if (idx < NN) {
        int n = idx;
        float y0 = Y[n * 4 + 0], y1 = Y[n * 4 + 1], y2 = Y[n * 4 + 2], y3 = Y[n * 4 + 3];
        #pragma unroll
        for (int b = 0; b < LLt; b++)
            g_Z[b][(long)n * LDZ + NN] = y0 * g_sm.DU[0][b] + y1 * g_sm.DU[1][b]
                                       + y2 * g_sm.DU[2][b] + y3 * g_sm.DU[3][b];
    }
}

// ---------------- P = A21 * inv32^T, then trailing -= P P^T. UR*16 = panel height ----
template<int UR>
__device__ __forceinline__ void panel_and_update(float (*sA)[129], float (*sI)[129],
                                                 int o, int tr, int tc)
{
    float pacc[UR][2];
    #pragma unroll
    for (int u = 0; u < UR; u++) { pacc[u][0] = 0.f; pacc[u][1] = 0.f; }
    #pragma unroll
    for (int q = 0; q < 32; q++) {
        float b0 = sI[o + tc][o + q];
        float b1 = sI[o + tc + 16][o + q];
        #pragma unroll
        for (int u = 0; u < UR; u++) {
            float a = sA[o + 32 + tr + 16 * u][o + q];
            pacc[u][0] += a * b0;
            pacc[u][1] += a * b1;
        }
    }
    __syncthreads();
    #pragma unroll
    for (int u = 0; u < UR; u++) {
        sA[o + 32 + tr + 16 * u][o + tc]      = pacc[u][0];
        sA[o + 32 + tr + 16 * u][o + tc + 16] = pacc[u][1];
    }
    __syncthreads();
    float upd[UR][UR];
    #pragma unroll
    for (int u = 0; u < UR; u++)
        #pragma unroll
        for (int v = 0; v < UR; v++) upd[u][v] = 0.f;
    #pragma unroll
    for (int q = 0; q < 32; q++) {
        float av[UR], bv[UR];
        #pragma unroll
        for (int u = 0; u < UR; u++) av[u] = sA[o + 32 + tr + 16 * u][o + q];
        #pragma unroll
        for (int v = 0; v < UR; v++) bv[v] = sA[o + 32 + tc + 16 * v][o + q];
        #pragma unroll
        for (int u = 0; u < UR; u++)
            #pragma unroll
            for (int v = 0; v < UR; v++)
                upd[u][v] += av[u] * bv[v];
    }
    #pragma unroll
    for (int u = 0; u < UR; u++)
        #pragma unroll
        for (int v = 0; v < UR; v++)
            sA[o + 32 + tr + 16 * u][o + 32 + tc + 16 * v] -= upd[u][v];
}

// ---------------- diag step (R9-proven): register Cholesky + smem-streamed inverse --
__global__ void __launch_bounds__(256)
diag_step(int k)
{
    extern __shared__ float dsm[];
    float (*sA)[129] = (float(*)[129])dsm;                    // 128x129 : A -> L
    float (*sX)[129] = (float(*)[129])(dsm + 128 * 129);      // 128x129 : invL
    float (*sT)[65]  = (float(*)[65])(dsm + 2 * 128 * 129);   // 64x65 scratch
    float* rd        = dsm + 2 * 128 * 129 + 64 * 65;         // 128 recip diag
    int b = blockIdx.x;
    int t = threadIdx.x;
    int lane = t & 31, warp = t >> 5;
    int tr = t >> 4, tc = t & 15;
    int off = k * NB;
    float* Lb = g_Lf[b];

    #pragma unroll 4
    for (int i = 0; i < 64; i++) {
        int e = t + i * 256;
        int r = e >> 7, c = e & 127;
        sA[r][c] = Lb[(long)(off + r) * NN + off + c];
        sX[r][c] = 0.f;
    }
    __syncthreads();

    for (int p = 0; p < 4; p++) {
        int o = p * 32;
        if (warp == 0) {
            float r[32];
            #pragma unroll
            for (int kk = 0; kk < 32; kk++) r[kk] = sA[o + lane][o + kk];
            #pragma unroll
            for (int j = 0; j < 32; j++) {
                float dj = __shfl_sync(0xffffffffu, r[j], j);
                float invd = rsqrtf(dj);
                float Lj = r[j] * invd;
                sA[o + lane][o + j] = (lane >= j) ? Lj : 0.f;
                if (lane == j) rd[o + j] = invd;
                #pragma unroll
                for (int kk = j + 1; kk < 32; kk++) {
                    float Lkj = __shfl_sync(0xffffffffu, Lj, kk);
                    r[kk] -= Lj * Lkj;
                }
            }
            __syncwarp();
            {
                int c = lane;
                sX[o + c][o + c] = rd[o + c];
                #pragma unroll
                for (int j = 1; j < 32; j++) {
                    float s0 = 0.f, s1 = 0.f;
                    #pragma unroll
                    for (int kk = 0; kk < j; kk++) {
                        float v = sA[o + j][o + kk] * sX[o + kk][o + c];
                        if (kk & 1) s1 += v; else s0 += v;
                    }
                    if (j > c) sX[o + j][o + c] = -(s0 + s1) * rd[o + j];
                }
            }
            __syncwarp();
        }
        __syncthreads();
        if (p == 0)      panel_and_update<6>(sA, sX, o, tr, tc);
        else if (p == 1) panel_and_update<4>(sA, sX, o, tr, tc);
        else if (p == 2) panel_and_update<2>(sA, sX, o, tr, tc);
        __syncthreads();
    }

    #pragma unroll 2
    for (int e = t; e < 2048; e += 256) {
        int g = e >> 10, i = (e >> 5) & 31, j = e & 31;
        int go = g * 64;
        float s0 = 0.f, s1 = 0.f;
        #pragma unroll
        for (int q = 0; q < 32; q += 2) {
            s0 += sA[go + 32 + i][go + q]     * sX[go + q][go + j];
            s1 += sA[go + 32 + i][go + q + 1] * sX[go + q + 1][go + j];
        }
        sT[g * 32 + i][j] = s0 + s1;
    }
    __syncthreads();
    #pragma unroll 2
    for (int e = t; e < 2048; e += 256) {
        int g = e >> 10, i = (e >> 5) & 31, j = e & 31;
        int go = g * 64;
        float s0 = 0.f, s1 = 0.f;
        #pragma unroll
        for (int q = 0; q < 32; q += 2) {
            s0 += sX[go + 32 + i][go + 32 + q]     * sT[g * 32 + q][j];
            s1 += sX[go + 32 + i][go + 32 + q + 1] * sT[g * 32 + q + 1][j];
        }
        sX[go + 32 + i][go + j] = -(s0 + s1);
    }
    __syncthreads();

    {
        float acc[4][4];
        #pragma unroll
        for (int u = 0; u < 4; u++)
            #pragma unroll
            for (int v = 0; v < 4; v++) acc[u][v] = 0.f;
        for (int q = 0; q < 64; q++) {
            float a4[4], b4[4];
            #pragma unroll
            for (int u = 0; u < 4; u++) a4[u] = sA[64 + tr * 4 + u][q];
            #pragma unroll
            for (int v = 0; v < 4; v++) b4[v] = sX[q][tc * 4 + v];
            #pragma unroll
            for (int u = 0; u < 4; u++)
                #pragma unroll
                for (int v = 0; v < 4; v++)
                    acc[u][v] += a4[u] * b4[v];
        }
        #pragma unroll
        for (int u = 0; u < 4; u++)
            #pragma unroll
            for (int v = 0; v < 4; v++)
                sT[tr * 4 + u][tc * 4 + v] = acc[u][v];
        __syncthreads();
        float ac2[4][4];
        #pragma unroll
        for (int u = 0; u < 4; u++)
            #pragma unroll
            for (int v = 0; v < 4; v++) ac2[u][v] = 0.f;
        for (int q = 0; q < 64; q++) {
            float a4[4], b4[4];
            #pragma unroll
            for (int u = 0; u < 4; u++) a4[u] = sX[64 + tr * 4 + u][64 + q];
            #pragma unroll
            for (int v = 0; v < 4; v++) b4[v] = sT[q][tc * 4 + v];
            #pragma unroll
            for (int u = 0; u < 4; u++)
                #pragma unroll
                for (int v = 0; v < 4; v++)
                    ac2[u][v] += a4[u] * b4[v];
        }
        #pragma unroll
        for (int u = 0; u < 4; u++)
            #pragma unroll
            for (int v = 0; v < 4; v++)
                sX[64 + tr * 4 + u][tc * 4 + v] = -ac2[u][v];
        __syncthreads();
    }

    #pragma unroll 4
    for (int i = 0; i < 64; i++) {
        int e = t + i * 256;
        int r = e >> 7, c = e & 127;
        g_invL[b][r * 128 + c] = sX[r][c];
    }
}

// ---------------- panel step as GEMM (float4 loads): L21 = A21*invL^T ; z'=invL*Z_k --
__global__ void __launch_bounds__(256, 2)
panel_gemm(int k)
{
    extern __shared__ float dsm[];
    float* As = dsm;                 // [2][16][UPAD]
    float* Bs = dsm + 2 * 16 * UPAD;
    int b = blockIdx.y;
    int mrem = NSTEP - 1 - k;
    int bi = blockIdx.x;
    bool isP = bi < mrem;
    int off = k * NB;
    float* Lb = g_Lf[b];
    float* Zb = g_Z[b];
    const float* IL = g_invL[b];
    int tid = threadIdx.x;
    int tr = tid >> 4, tc = tid & 15;
    int rowbase = off + NB + bi * 128;
    int zcolbase = (bi - mrem) * 128;

    // float4 load mappings
    int m4 = tid >> 2, kq = (tid & 3) * 4;        // A-style: rows of 16 floats
    int kz4 = tid >> 5, nq = (tid & 31) * 4;      // Z-style: rows of 128 floats

    float acc[8][8];
    #pragma unroll
    for (int u = 0; u < 8; u++)
        #pragma unroll
        for (int v = 0; v < 8; v++) acc[u][v] = 0.f;

    float4 va[2], vb[2];
    #pragma unroll
    for (int i = 0; i < 2; i++) {
        int m = m4 + i * 64;
        if (isP) {
            va[i] = *(const float4*)&Lb[(long)(rowbase + m) * NN + off + kq];
            vb[i] = *(const float4*)&IL[m * 128 + kq];
        } else {
            va[i] = *(const float4*)&IL[m * 128 + kq];
            int kz = kz4 + i * 8;
            vb[i] = *(const float4*)&Zb[(long)(off + kz) * LDZ + zcolbase + nq];
        }
    }
    #pragma unroll
    for (int i = 0; i < 2; i++) {
        int m = m4 + i * 64;
        As[(kq + 0) * UPAD + m] = va[i].x;
        As[(kq + 1) * UPAD + m] = va[i].y;
        As[(kq + 2) * UPAD + m] = va[i].z;
        As[(kq + 3) * UPAD + m] = va[i].w;
        if (isP) {
            Bs[(kq + 0) * UPAD + m] = vb[i].x;
            Bs[(kq + 1) * UPAD + m] = vb[i].y;
            Bs[(kq + 2) * UPAD + m] = vb[i].z;
            Bs[(kq + 3) * UPAD + m] = vb[i].w;
        } else {
            int kz = kz4 + i * 8;
            *(float4*)&Bs[kz * UPAD + nq] = vb[i];
        }
    }
    __syncthreads();

    for (int it = 0; it < 8; it++) {
        int p = it & 1;
        if (it + 1 < 8) {
            int k0 = (it + 1) * 16;
            #pragma unroll
            for (int i = 0; i < 2; i++) {
                int m = m4 + i * 64;
                if (isP) {
                    va[i] = *(const float4*)&Lb[(long)(rowbase + m) * NN + off + k0 + kq];
                    vb[i] = *(const float4*)&IL[m * 128 + k0 + kq];
                } else {
                    va[i] = *(const float4*)&IL[m * 128 + k0 + kq];
                    int kz = kz4 + i * 8;
                    vb[i] = *(const float4*)&Zb[(long)(off + k0 + kz) * LDZ + zcolbase + nq];
                }
            }
        }
        float* Ap = As + p * 16 * UPAD;
        float* Bp = Bs + p * 16 * UPAD;
        #pragma unroll
        for (int kk = 0; kk < 16; kk++) {
            float a[8], bb[8];
            *reinterpret_cast<float4*>(&a[0])  = *reinterpret_cast<float4*>(Ap + kk * UPAD + tr * 4);
            *reinterpret_cast<float4*>(&a[4])  = *reinterpret_cast<float4*>(Ap + kk * UPAD + 64 + tr * 4);
            *reinterpret_cast<float4*>(&bb[0]) = *reinterpret_cast<float4*>(Bp + kk * UPAD + tc * 4);
            *reinterpret_cast<float4*>(&bb[4]) = *reinterpret_cast<float4*>(Bp + kk * UPAD + 64 + tc * 4);
            #pragma unroll
            for (int u = 0; u < 8; u++)
                #pragma unroll
                for (int v = 0; v < 8; v++)
                    acc[u][v] += a[u] * bb[v];
        }
        if (it + 1 < 8) {
            int q = (it + 1) & 1;
            float* Aq = As + q * 16 * UPAD;
            float* Bq = Bs + q * 16 * UPAD;
            #pragma unroll
            for (int i = 0; i < 2; i++) {
                int m = m4 + i * 64;
                Aq[(kq + 0) * UPAD + m] = va[i].x;
                Aq[(kq + 1) * UPAD + m] = va[i].y;
                Aq[(kq + 2) * UPAD + m] = va[i].z;
                Aq[(kq + 3) * UPAD + m] = va[i].w;
                if (isP) {
                    Bq[(kq + 0) * UPAD + m] = vb[i].x;
                    Bq[(kq + 1) * UPAD + m] = vb[i].y;
                    Bq[(kq + 2) * UPAD + m] = vb[i].z;
                    Bq[(kq + 3) * UPAD + m] = vb[i].w;
                } else {
                    int kz = kz4 + i * 8;
                    *(float4*)&Bq[kz * UPAD + nq] = vb[i];
                }
            }
        }
        __syncthreads();
    }

    #pragma unroll
    for (int u = 0; u < 8; u++) {
        int row = ((u < 4) ? tr * 4 + u : 64 + tr * 4 + (u - 4));
        #pragma unroll
        for (int v = 0; v < 8; v++) {
            int n = ((v < 4) ? tc * 4 + v : 64 + tc * 4 + (v - 4));
            if (isP) {
                Lb[(long)(rowbase + row) * NN + off + n] = acc[u][v];
            } else {
                int col = zcolbase + n;
                if (col < NRHS)
                    Zb[(long)(off + row) * LDZ + col] = acc[u][v];
            }
        }
    }
}

// ---------------- merged trailing update (float4 loads, K=128, double-buffered) ----
// mode 0: ONLY tile (0,0); mode 1: all except tile (0,0).
__global__ void __launch_bounds__(256, 2)
ustep(int k, int mode)
{
    extern __shared__ float dsm[];
    float* As = dsm;
    float* Bs = dsm + 2 * 16 * UPAD;
    int b = blockIdx.z;
    int mrem = NSTEP - 1 - k;
    int mt = mrem;
    int bi = blockIdx.x, bj = blockIdx.y;
    bool isA = bj < mt;
    if (isA && bj > bi) return;
    if (mode == 1 && isA && bi == 0 && bj == 0) return;
    int rowoff = (k + 1) * NB;
    float* Lb = g_Lf[b];
    float* Zb = g_Z[b];
    int tid = threadIdx.x;
    int tr = tid >> 4, tc = tid & 15;
    int zcolbase = (bj - mt) * 128;

    int m4 = tid >> 2, kq = (tid & 3) * 4;
    int kz4 = tid >> 5, nq = (tid & 31) * 4;

    float acc[8][8];
    #pragma unroll
    for (int u = 0; u < 8; u++)
        #pragma unroll
        for (int v = 0; v < 8; v++) acc[u][v] = 0.f;

    const long arow = (long)(rowoff + bi * 128) * NN + k * NB;
    const long brow = isA ? (long)(rowoff + bj * 128) * NN + k * NB : 0;

    float4 va[2], vb[2];
    #pragma unroll
    for (int i = 0; i < 2; i++) {
        int m = m4 + i * 64;
        va[i] = *(const float4*)&Lb[arow + (long)m * NN + kq];
        if (isA) vb[i] = *(const float4*)&Lb[brow + (long)m * NN + kq];
        else {
            int kz = kz4 + i * 8;
            vb[i] = *(const float4*)&Zb[(long)(k * NB + kz) * LDZ + zcolbase + nq];
        }
    }
    #pragma unroll
    for (int i = 0; i < 2; i++) {
        int m = m4 + i * 64;
        As[(kq + 0) * UPAD + m] = va[i].x;
        As[(kq + 1) * UPAD + m] = va[i].y;
        As[(kq + 2) * UPAD + m] = va[i].z;
        As[(kq + 3) * UPAD + m] = va[i].w;
        if (isA) {
            Bs[(kq + 0) * UPAD + m] = vb[i].x;
            Bs[(kq + 1) * UPAD + m] = vb[i].y;
            Bs[(kq + 2) * UPAD + m] = vb[i].z;
            Bs[(kq + 3) * UPAD + m] = vb[i].w;
        } else {
            int kz = kz4 + i * 8;
            *(float4*)&Bs[kz * UPAD + nq] = vb[i];
        }
    }
    __syncthreads();

    for (int it = 0; it < 8; it++) {
        int p = it & 1;
        if (it + 1 < 8) {
            int k0 = (it + 1) * 16;
            #pragma unroll
            for (int i = 0; i < 2; i++) {
                int m = m4 + i * 64;
                va[i] = *(const float4*)&Lb[arow + (long)m * NN + k0 + kq];
                if (isA) vb[i] = *(const float4*)&Lb[brow + (long)m * NN + k0 + kq];
                else {
                    int kz = kz4 + i * 8;
                    vb[i] = *(const float4*)&Zb[(long)(k * NB + k0 + kz) * LDZ + zcolbase + nq];
                }
            }
        }
        float* Ap = As + p * 16 * UPAD;
        float* Bp = Bs + p * 16 * UPAD;
        #pragma unroll
        for (int kk = 0; kk < 16; kk++) {
            float a[8], bb[8];
            *reinterpret_cast<float4*>(&a[0])  = *reinterpret_cast<float4*>(Ap + kk * UPAD + tr * 4);
            *reinterpret_cast<float4*>(&a[4])  = *reinterpret_cast<float4*>(Ap + kk * UPAD + 64 + tr * 4);
            *reinterpret_cast<float4*>(&bb[0]) = *reinterpret_cast<float4*>(Bp + kk * UPAD + tc * 4);
            *reinterpret_cast<float4*>(&bb[4]) = *reinterpret_cast<float4*>(Bp + kk * UPAD + 64 + tc * 4);
            #pragma unroll
            for (int u = 0; u < 8; u++)
                #pragma unroll
                for (int v = 0; v < 8; v++)
                    acc[u][v] += a[u] * bb[v];
        }
        if (it + 1 < 8) {
            int q = (it + 1) & 1;
            float* Aq = As + q * 16 * UPAD;
            float* Bq = Bs + q * 16 * UPAD;
            #pragma unroll
            for (int i = 0; i < 2; i++) {
                int m = m4 + i * 64;
                Aq[(kq + 0) * UPAD + m] = va[i].x;
                Aq[(kq + 1) * UPAD + m] = va[i].y;
                Aq[(kq + 2) * UPAD + m] = va[i].z;
                Aq[(kq + 3) * UPAD + m] = va[i].w;
                if (isA) {
                    Bq[(kq + 0) * UPAD + m] = vb[i].x;
                    Bq[(kq + 1) * UPAD + m] = vb[i].y;
                    Bq[(kq + 2) * UPAD + m] = vb[i].z;
                    Bq[(kq + 3) * UPAD + m] = vb[i].w;
                } else {
                    int kz = kz4 + i * 8;
                    *(float4*)&Bq[kz * UPAD + nq] = vb[i];
                }
            }
        }
        __syncthreads();
    }

    #pragma unroll
    for (int u = 0; u < 8; u++) {
        int row = bi * 128 + ((u < 4) ? tr * 4 + u : 64 + tr * 4 + (u - 4));
        #pragma unroll
        for (int v = 0; v < 8; v++) {
            int n = ((v < 4) ? tc * 4 + v : 64 + tc * 4 + (v - 4));
            if (isA) {
                int col = bj * 128 + n;
                Lb[(long)(rowoff + row) * NN + rowoff + col] -= acc[u][v];
            } else {
                int col = zcolbase + n;
                if (col < NRHS)
                    Zb[(long)(rowoff + row) * LDZ + col] -= acc[u][v];
            }
        }
    }
}

// ---------------- W = T^T T (batched syrk, float4 loads, K-split x2) ----------
__global__ void __launch_bounds__(256, 2)
syrk_W()
{
    extern __shared__ float dsm[];
    float* As = dsm;
    float* Bs = dsm + 2 * 16 * UPAD;
    int bi = blockIdx.x, bj = blockIdx.y;
    int zz = blockIdx.z;
    int b = zz & 3, half = zz >> 2;
    if (bj > bi) return;
    const float* Zb = g_Z[b];
    float* Wb = half ? g_W2[b] : g_W[b];
    int kbase = half * 32;
    int tid = threadIdx.x;
    int tr = tid >> 4, tc = tid & 15;
    int kk4 = tid >> 5, mq = (tid & 31) * 4;    // 2 float4 per thread per operand

    float acc[8][8];
    #pragma unroll
    for (int u = 0; u < 8; u++)
        #pragma unroll
        for (int v = 0; v < 8; v++) acc[u][v] = 0.f;

    float4 va[2], vb[2];
    #pragma unroll
    for (int i = 0; i < 2; i++) {
        int kk = kk4 + i * 8;
        va[i] = *(const float4*)&Zb[(long)(kbase * 16 + kk) * LDZ + bi * 128 + mq];
        vb[i] = *(const float4*)&Zb[(long)(kbase * 16 + kk) * LDZ + bj * 128 + mq];
    }
    #pragma unroll
    for (int i = 0; i < 2; i++) {
        int kk = kk4 + i * 8;
        *(float4*)&As[kk * UPAD + mq] = va[i];
        *(float4*)&Bs[kk * UPAD + mq] = vb[i];
    }
    __syncthreads();

    for (int it = 0; it < 32; it++) {
        int p = it & 1;
        if (it + 1 < 32) {
            int k0 = (kbase + it + 1) * 16;
            #pragma unroll
            for (int i = 0; i < 2; i++) {
                int kk = kk4 + i * 8;
                va[i] = *(const float4*)&Zb[(long)(k0 + kk) * LDZ + bi * 128 + mq];
                vb[i] = *(const float4*)&Zb[(long)(k0 + kk) * LDZ + bj * 128 + mq];
            }
        }
        float* Ap = As + p * 16 * UPAD;
        float* Bp = Bs + p * 16 * UPAD;
        #pragma unroll
        for (int kk = 0; kk < 16; kk++) {
            float a[8], bb[8];
            *reinterpret_cast<float4*>(&a[0])  = *reinterpret_cast<float4*>(Ap + kk * UPAD + tr * 4);
            *reinterpret_cast<float4*>(&a[4])  = *reinterpret_cast<float4*>(Ap + kk * UPAD + 64 + tr * 4);
            *reinterpret_cast<float4*>(&bb[0]) = *reinterpret_cast<float4*>(Bp + kk * UPAD + tc * 4);
            *reinterpret_cast<float4*>(&bb[4]) = *reinterpret_cast<float4*>(Bp + kk * UPAD + 64 + tc * 4);
            #pragma unroll
            for (int u = 0; u < 8; u++)
                #pragma unroll
                for (int v = 0; v < 8; v++)
                    acc[u][v] += a[u] * bb[v];
        }
        if (it + 1 < 32) {
            int q = (it + 1) & 1;
            float* Aq = As + q * 16 * UPAD;
            float* Bq = Bs + q * 16 * UPAD;
            #pragma unroll
            for (int i = 0; i < 2; i++) {
                int kk = kk4 + i * 8;
                *(float4*)&Aq[kk * UPAD + mq] = va[i];
                *(float4*)&Bq[kk * UPAD + mq] = vb[i];
            }
        }
        __syncthreads();
    }

    #pragma unroll
    for (int u = 0; u < 8; u++) {
        int row = bi * 128 + ((u < 4) ? tr * 4 + u : 64 + tr * 4 + (u - 4));
        #pragma unroll
        for (int v = 0; v < 8; v++) {
            int col = bj * 128 + ((v < 4) ? tc * 4 + v : 64 + tc * 4 + (v - 4));
            float o = acc[u][v];
            Wb[(long)row * NN + col] = o;
            if (bi != bj) Wb[(long)col * NN + row] = o;
        }
    }
}

// ---------------- fmean: Fp_b[m] = sum_n T_b[n][m] * u_b[n] ----------------
__global__ void fmean_dot()
{
    int b = blockIdx.y;
    int m = blockIdx.x * 256 + threadIdx.x;
    __shared__ float su[NN];
    const float* Zb = g_Z[b];
    for (int n = threadIdx.x; n < NN; n += 256) su[n] = Zb[(long)n * LDZ + NN];
    __syncthreads();
    float a0 = 0.f, a1 = 0.f, a2 = 0.f, a3 = 0.f;
    #pragma unroll 4
    for (int n = 0; n < NN; n += 4) {
        a0 += Zb[(long)n * LDZ + m]       * su[n];
        a1 += Zb[(long)(n + 1) * LDZ + m] * su[n + 1];
        a2 += Zb[(long)(n + 2) * LDZ + m] * su[n + 2];
        a3 += Zb[(long)(n + 3) * LDZ + m] * su[n + 3];
    }
    g_Fp[b][m] = (a0 + a1) + (a2 + a3);
}

__global__ void fmean_comb(float* __restrict__ out)
{
    int m = blockIdx.x * 256 + threadIdx.x;
    if (m >= NN) return;
    float f0 = g_Fp[0][m], f1 = g_Fp[1][m], f2 = g_Fp[2][m], f3 = g_Fp[3][m];
    #pragma unroll
    for (int q = 0; q < LLt; q++) {
        float v = f0 * g_sm.G[0][q] + f1 * g_sm.G[1][q]
                + f2 * g_sm.G[2][q] + f3 * g_sm.G[3][q];
        out[(long)q * NN + m] = v;
        out[4096L + 2L * 16777216L + (long)m * 4 + q] = v;
    }
}

// ---------------- fvar assembly (sums the two K-half W partials) --------------
__global__ void fvar_kernel(float* __restrict__ out)
{
    int idx = blockIdx.x * 256 + threadIdx.x;
    int a  = idx >> 8;
    int b4 = idx & 255;
    long vi = (long)a * 256 + b4;
    float4 vt = reinterpret_cast<const float4*>(g_Ctt)[vi];
    float4 w0 = reinterpret_cast<const float4*>(g_W[0])[vi];
    float4 w1 = reinterpret_cast<const float4*>(g_W[1])[vi];
    float4 w2 = reinterpret_cast<const float4*>(g_W[2])[vi];
    float4 w3 = reinterpret_cast<const float4*>(g_W[3])[vi];
    float4 x0 = reinterpret_cast<const float4*>(g_W2[0])[vi];
    float4 x1 = reinterpret_cast<const float4*>(g_W2[1])[vi];
    float4 x2 = reinterpret_cast<const float4*>(g_W2[2])[vi];
    float4 x3 = reinterpret_cast<const float4*>(g_W2[3])[vi];
    w0.x += x0.x; w0.y += x0.y; w0.z += x0.z; w0.w += x0.w;
    w1.x += x1.x; w1.y += x1.y; w1.z += x1.z; w1.w += x1.w;
    w2.x += x2.x; w2.y += x2.y; w2.z += x2.z; w2.w += x2.w;
    w3.x += x3.x; w3.y += x3.y; w3.z += x3.z; w3.w += x3.w;
    float4* fv = reinterpret_cast<float4*>(out + 4096);
    #pragma unroll
    for (int q = 0; q < 4; q++) {
        #pragma unroll
        for (int r = 0; r < 4; r++) {
            float cb = g_sm.B[q][r];
            float c0 = g_sm.G[0][q] * g_sm.G[0][r];
            float c1 = g_sm.G[1][q] * g_sm.G[1][r];
            float c2 = g_sm.G[2][q] * g_sm.G[2][r];
            float c3 = g_sm.G[3][q] * g_sm.G[3][r];
            float4 v;
            v.x = cb * vt.x - c0 * w0.x - c1 * w1.x - c2 * w2.x - c3 * w3.x;
            v.y = cb * vt.y - c0 * w0.y - c1 * w1.y - c2 * w2.y - c3 * w3.y;
            v.z = cb * vt.z - c0 * w0.z - c1 * w1.z - c2 * w2.z - c3 * w3.z;
            v.w = cb * vt.w - c0 * w0.w - c1 * w1.w - c2 * w2.w - c3 * w3.w;
            fv[(long)(q * NN + a) * 1024 + r * 256 + b4] = v;
        }
    }
}

// ---------------- noise output (zeros + diagonal in one pass) ----------------
__global__ void noise_fill(float* __restrict__ out)
{
    long i = (long)blockIdx.x * 256 + threadIdx.x;
    long base = i * 4;
    int row = (int)(base >> 12);
    int col0 = (int)(base & 4095);
    float4 v = make_float4(0.f, 0.f, 0.f, 0.f);
    if (row >= col0 && row < col0 + 4)
        reinterpret_cast<float*>(&v)[row - col0] = g_sm.dn[row >> 10];
    reinterpret_cast<float4*>(out + 4096 + 16777216L)[i] = v;
}

// ---------------- launcher (multi-stream graph: diag(k+1) || ustep_rest(k)) ----
extern "C" void kernel_launch(void* const* d_in, const int* in_sizes, int n_in,
                              void* d_out, int out_size)
{
    const float* X      = (const float*)d_in[0];
    const float* tX     = (const float*)d_in[1];
    const float* Y      = (const float*)d_in[2];
    const float* lnoise = (const float*)d_in[3];
    const float* cf     = (const float*)d_in[4];
    const float* lvar   = (const float*)d_in[5];
    const float* lls    = (const float*)d_in[6];
    float* out = (float*)d_out;
    int l = in_sizes[3];
    int rank = in_sizes[4] / l;
    (void)l;

    const int DSMEM = (2 * 128 * 129 + 64 * 65 + 128) * 4;   // 149248 B
    const int GSMEM = 2 * 2 * 16 * UPAD * 4;                 // 67584 B
    cudaFuncSetAttribute(diag_step,  cudaFuncAttributeMaxDynamicSharedMemorySize, DSMEM);
    cudaFuncSetAttribute(panel_gemm, cudaFuncAttributeMaxDynamicSharedMemorySize, GSMEM);
    cudaFuncSetAttribute(ustep,      cudaFuncAttributeMaxDynamicSharedMemorySize, GSMEM);
    cudaFuncSetAttribute(syrk_W,     cudaFuncAttributeMaxDynamicSharedMemorySize, GSMEM);

    cudaStream_t s2;
    cudaStreamCreateWithFlags(&s2, cudaStreamNonBlocking);
    cudaEvent_t evA, evB;
    cudaEventCreateWithFlags(&evA, cudaEventDisableTiming);
    cudaEventCreateWithFlags(&evB, cudaEventDisableTiming);

    small_setup<<<1, 32>>>(lnoise, cf, lvar, lls, rank);
    rbf_all<<<NN * NN / 256, 256>>>(X, tX, Y);
    noise_fill<<<16384, 256>>>(out);
    diag_step<<<LLt, 256, DSMEM>>>(0);

    // factor + forward-solve sweep; diag(k+1) overlapped with ustep_rest(k) on s2
    for (int k = 0; k < NSTEP; k++) {
        int mrem = NSTEP - 1 - k;
        panel_gemm<<<dim3(mrem + 9, LLt), 256, GSMEM>>>(k);
        if (mrem > 0) {
            ustep<<<dim3(1, 1, LLt), 256, GSMEM>>>(k, 0);            // tile (0,0) only
            cudaEventRecord(evA, 0);
            cudaStreamWaitEvent(s2, evA, 0);
            diag_step<<<LLt, 256, DSMEM, s2>>>(k + 1);               // overlapped
            cudaEventRecord(evB, s2);
            ustep<<<dim3(mrem, mrem + 9, LLt), 256, GSMEM>>>(k, 1);  // rest of tiles
            cudaStreamWaitEvent(0, evB, 0);
        }
    }

    // W_i = T_i^T T_i  (batched syrk, K-split x2: 288 working CTAs)
    syrk_W<<<dim3(8, 8, LLt * 2), 256, GSMEM>>>();

    // fmean = sum_i G[i][q] * T_i^T u_i
    fmean_dot<<<dim3(4, LLt), 256>>>();
    fmean_comb<<<4, 256>>>(out);

    // fvar and noise outputs
    fvar_kernel<<<1024, 256>>>(out);
}

// round 16
// speedup vs baseline: 1.1951x; 1.0302x over previous
#include <cuda_runtime.h>
#include <math.h>

#define NN 1024           // N = N_ = 1024 training/test points
#define LLt 4             // l = 4 tasks
#define DD 8              // input dim
#define NB 128            // factorization block size
#define NSTEP 8           // NN / NB
#define LDZ 1152          // padded leading dim for Z (9 full 128-col tiles)
#define NRHS 1025         // 1024 Cx columns + 1 ytil column
#define UPAD 132          // smem tile row padding for gemm kernels

// ---------------- device scratch (static: no allocation allowed) ----------------
__device__ float g_Ctt[NN * NN];        // rbf(test_X, test_X)
__device__ float g_Lf[LLt][NN * NN];    // per-batch A_i = s_i*C + I -> L panels in-place
__device__ float g_Z[LLt][NN * LDZ];    // per-batch RHS [Cx | ytil_i]; cols >= NRHS stay 0
__device__ float g_W[LLt][NN * NN];     // W_i partial (K half 0)
__device__ float g_W2[LLt][NN * NN];    // W_i partial (K half 1)
__device__ float g_Fp[LLt][NN];         // per-batch T_i^T u_i
__device__ float g_invL[LLt][NB * NB];  // per-step inverse of diag block

struct Small {
    float s[LLt];          // eigenvalues of B'
    float G[LLt][LLt];     // G[i][q] = (U^T D^{-1/2} B)[i][q]
    float B[LLt][LLt];     // task_K
    float dn[LLt];         // exp(log_noise)
    float DU[LLt][LLt];    // DU[p][i] = dns[p]*U[p][i]
    float inv2ls2;         // 0.5 / ls^2
};
__device__ Small g_sm;

// ---------------- small setup: task matrix, 4x4 Jacobi eig ----------------
__global__ void small_setup(const float* __restrict__ log_noise,
                            const float* __restrict__ covar_factor,
                            const float* __restrict__ log_var,
                            const float* __restrict__ log_ls, int rank)
{
    if (threadIdx.x != 0 || blockIdx.x != 0) return;
    double dn[LLt], dns[LLt];
    for (int p = 0; p < LLt; p++) {
        dn[p]  = exp((double)log_noise[p]);
        dns[p] = exp(-0.5 * (double)log_noise[p]);
    }
    double B[LLt][LLt];
    for (int q = 0; q < LLt; q++)
        for (int r = 0; r < LLt; r++) {
            double s = 0.0;
            for (int k = 0; k < rank; k++)
                s += (double)covar_factor[q * rank + k] * (double)covar_factor[r * rank + k];
            if (q == r) s += exp((double)log_var[q]);
            B[q][r] = s;
        }
    double A[LLt][LLt], V[LLt][LLt];
    for (int q = 0; q < LLt; q++)
        for (int r = 0; r < LLt; r++) {
            A[q][r] = dns[q] * B[q][r] * dns[r];
            V[q][r] = (q == r) ? 1.0 : 0.0;
        }
    for (int sweep = 0; sweep < 40; sweep++) {
        for (int p = 0; p < LLt - 1; p++)
            for (int q = p + 1; q < LLt; q++) {
                double apq = A[p][q];
                if (fabs(apq) < 1e-300) continue;
                double theta = 0.5 * atan2(2.0 * apq, A[q][q] - A[p][p]);
                double c = cos(theta), s = sin(theta);
                for (int k = 0; k < LLt; k++) {
                    double akp = A[k][p], akq = A[k][q];
                    A[k][p] = c * akp - s * akq;
                    A[k][q] = s * akp + c * akq;
                }
                for (int k = 0; k < LLt; k++) {
                    double apk = A[p][k], aqk = A[q][k];
                    A[p][k] = c * apk - s * aqk;
                    A[q][k] = s * apk + c * aqk;
                }
                for (int k = 0; k < LLt; k++) {
                    double vkp = V[k][p], vkq = V[k][q];
                    V[k][p] = c * vkp - s * vkq;
                    V[k][q] = s * vkp + c * vkq;
                }
            }
    }
    for (int i = 0; i < LLt; i++) g_sm.s[i] = (float)A[i][i];
    for (int p = 0; p < LLt; p++)
        for (int i = 0; i < LLt; i++)
            g_sm.DU[p][i] = (float)(dns[p] * V[p][i]);
    for (int i = 0; i < LLt; i++)
        for (int q = 0; q < LLt; q++) {
            double s = 0.0;
            for (int p = 0; p < LLt; p++) s += V[p][i] * dns[p] * B[p][q];
            g_sm.G[i][q] = (float)s;
        }
    for (int q = 0; q < LLt; q++)
        for (int r = 0; r < LLt; r++) g_sm.B[q][r] = (float)B[q][r];
    for (int p = 0; p < LLt; p++) g_sm.dn[p] = (float)dn[p];
    g_sm.inv2ls2 = (float)(0.5 * exp(-2.0 * (double)log_ls[0]));
}

// ---------------- merged RBF: A_b, Z (Cx cols + ytil col), Ctt ----------------
__global__ void rbf_all(const float* __restrict__ X, const float* __restrict__ tX,
                        const float* __restrict__ Y)
{
    int idx = blockIdx.x * 256 + threadIdx.x;
    int i = idx >> 10, j = idx & 1023;
    float dAA = 0.f, dAx = 0.f, dtt = 0.f;
    #pragma unroll
    for (int d = 0; d < DD; d++) {
        float xi = X[i * DD + d], xj = X[j * DD + d];
        float ti = tX[i * DD + d], tj = tX[j * DD + d];
        float a = xi - xj; dAA += a * a;
        float b = xi - tj; dAx += b * b;
        float c = ti - tj; dtt += c * c;
    }
    float s2 = g_sm.inv2ls2;
    float vAA = expf(-dAA * s2);
    float vAx = expf(-dAx * s2);
    g_Ctt[idx] = expf(-dtt * s2);
    float diag = (i == j) ? 1.f : 0.f;
    long zoff = (long)i * LDZ + j;
    #pragma unroll
    for (int b = 0; b < LLt; b++) {
        g_Lf[b][idx] = g_sm.s[b] * vAA + diag;
        g_Z[b][zoff] = vAx;
    }
    if (idx < NN) {
        int n = idx;
        float y0 = Y[n * 4 + 0], y1 = Y[n * 4 + 1], y2 = Y[n * 4 + 2], y3 = Y[n * 4 + 3];
        #pragma unroll
        for (int b = 0; b < LLt; b++)
            g_Z[b][(long)n * LDZ + NN] = y0 * g_sm.DU[0][b] + y1 * g_sm.DU[1][b]
                                       + y2 * g_sm.DU[2][b] + y3 * g_sm.DU[3][b];
    }
}

// ---------------- P = A21 * inv32^T, then trailing -= P P^T. UR*16 = panel height ----
template<int UR>
__device__ __forceinline__ void panel_and_update(float (*sA)[129], float (*sI)[129],
                                                 int o, int tr, int tc)
{
    float pacc[UR][2];
    #pragma unroll
    for (int u = 0; u < UR; u++) { pacc[u][0] = 0.f; pacc[u][1] = 0.f; }
    #pragma unroll
    for (int q = 0; q < 32; q++) {
        float b0 = sI[o + tc][o + q];
        float b1 = sI[o + tc + 16][o + q];
        #pragma unroll
        for (int u = 0; u < UR; u++) {
            float a = sA[o + 32 + tr + 16 * u][o + q];
            pacc[u][0] += a * b0;
            pacc[u][1] += a * b1;
        }
    }
    __syncthreads();
    #pragma unroll
    for (int u = 0; u < UR; u++) {
        sA[o + 32 + tr + 16 * u][o + tc]      = pacc[u][0];
        sA[o + 32 + tr + 16 * u][o + tc + 16] = pacc[u][1];
    }
    __syncthreads();
    float upd[UR][UR];
    #pragma unroll
    for (int u = 0; u < UR; u++)
        #pragma unroll
        for (int v = 0; v < UR; v++) upd[u][v] = 0.f;
    #pragma unroll
    for (int q = 0; q < 32; q++) {
        float av[UR], bv[UR];
        #pragma unroll
        for (int u = 0; u < UR; u++) av[u] = sA[o + 32 + tr + 16 * u][o + q];
        #pragma unroll
        for (int v = 0; v < UR; v++) bv[v] = sA[o + 32 + tc + 16 * v][o + q];
        #pragma unroll
        for (int u = 0; u < UR; u++)
            #pragma unroll
            for (int v = 0; v < UR; v++)
                upd[u][v] += av[u] * bv[v];
    }
    #pragma unroll
    for (int u = 0; u < UR; u++)
        #pragma unroll
        for (int v = 0; v < UR; v++)
            sA[o + 32 + tr + 16 * u][o + 32 + tc + 16 * v] -= upd[u][v];
}

// ---------------- diag step: self-contained (applies own rank-128 update) ------
// For k>0: loads panel P = L[rows off..off+127, cols off-128..off-1] (written by
// panel_gemm(k-1)) and computes sA -= P P^T before factoring. Depends ONLY on
// panel_gemm(k-1), so it overlaps the whole ustep(k-1).
__global__ void __launch_bounds__(256)
diag_step(int k)
{
    extern __shared__ float dsm[];
    float (*sA)[129] = (float(*)[129])dsm;                    // 128x129 : A -> L
    float (*sX)[129] = (float(*)[129])(dsm + 128 * 129);      // 128x129 : P, then invL
    float (*sT)[65]  = (float(*)[65])(dsm + 2 * 128 * 129);   // 64x65 scratch
    float* rd        = dsm + 2 * 128 * 129 + 64 * 65;         // 128 recip diag
    int b = blockIdx.x;
    int t = threadIdx.x;
    int lane = t & 31, warp = t >> 5;
    int tr = t >> 4, tc = t & 15;
    int off = k * NB;
    float* Lb = g_Lf[b];

    // load stale A_kk; load P into sX if k>0
    #pragma unroll 4
    for (int i = 0; i < 64; i++) {
        int e = t + i * 256;
        int r = e >> 7, c = e & 127;
        sA[r][c] = Lb[(long)(off + r) * NN + off + c];
        if (k > 0) sX[r][c] = Lb[(long)(off + r) * NN + (off - NB) + c];
    }
    __syncthreads();

    if (k > 0) {
        // sA -= P P^T, 8x8 register tiles
        float acc[8][8];
        #pragma unroll
        for (int u = 0; u < 8; u++)
            #pragma unroll
            for (int v = 0; v < 8; v++) acc[u][v] = 0.f;
        for (int q = 0; q < 128; q++) {
            float a8[8], b8[8];
            #pragma unroll
            for (int u = 0; u < 8; u++) a8[u] = sX[tr * 8 + u][q];
            #pragma unroll
            for (int v = 0; v < 8; v++) b8[v] = sX[tc * 8 + v][q];
            #pragma unroll
            for (int u = 0; u < 8; u++)
                #pragma unroll
                for (int v = 0; v < 8; v++)
                    acc[u][v] += a8[u] * b8[v];
        }
        __syncthreads();
        #pragma unroll
        for (int u = 0; u < 8; u++)
            #pragma unroll
            for (int v = 0; v < 8; v++)
                sA[tr * 8 + u][tc * 8 + v] -= acc[u][v];
    }
    // zero sX for invL accumulation
    #pragma unroll 4
    for (int i = 0; i < 64; i++) {
        int e = t + i * 256;
        sX[e >> 7][e & 127] = 0.f;
    }
    __syncthreads();

    for (int p = 0; p < 4; p++) {
        int o = p * 32;
        if (warp == 0) {
            float r[32];
            #pragma unroll
            for (int kk = 0; kk < 32; kk++) r[kk] = sA[o + lane][o + kk];
            #pragma unroll
            for (int j = 0; j < 32; j++) {
                float dj = __shfl_sync(0xffffffffu, r[j], j);
                float invd = rsqrtf(dj);
                float Lj = r[j] * invd;
                sA[o + lane][o + j] = (lane >= j) ? Lj : 0.f;
                if (lane == j) rd[o + j] = invd;
                #pragma unroll
                for (int kk = j + 1; kk < 32; kk++) {
                    float Lkj = __shfl_sync(0xffffffffu, Lj, kk);
                    r[kk] -= Lj * Lkj;
                }
            }
            __syncwarp();
            {
                int c = lane;
                sX[o + c][o + c] = rd[o + c];
                #pragma unroll
                for (int j = 1; j < 32; j++) {
                    float s0 = 0.f, s1 = 0.f;
                    #pragma unroll
                    for (int kk = 0; kk < j; kk++) {
                        float v = sA[o + j][o + kk] * sX[o + kk][o + c];
                        if (kk & 1) s1 += v; else s0 += v;
                    }
                    if (j > c) sX[o + j][o + c] = -(s0 + s1) * rd[o + j];
                }
            }
            __syncwarp();
        }
        __syncthreads();
        if (p == 0)      panel_and_update<6>(sA, sX, o, tr, tc);
        else if (p == 1) panel_and_update<4>(sA, sX, o, tr, tc);
        else if (p == 2) panel_and_update<2>(sA, sX, o, tr, tc);
        __syncthreads();
    }

    #pragma unroll 2
    for (int e = t; e < 2048; e += 256) {
        int g = e >> 10, i = (e >> 5) & 31, j = e & 31;
        int go = g * 64;
        float s0 = 0.f, s1 = 0.f;
        #pragma unroll
        for (int q = 0; q < 32; q += 2) {
            s0 += sA[go + 32 + i][go + q]     * sX[go + q][go + j];
            s1 += sA[go + 32 + i][go + q + 1] * sX[go + q + 1][go + j];
        }
        sT[g * 32 + i][j] = s0 + s1;
    }
    __syncthreads();
    #pragma unroll 2
    for (int e = t; e < 2048; e += 256) {
        int g = e >> 10, i = (e >> 5) & 31, j = e & 31;
        int go = g * 64;
        float s0 = 0.f, s1 = 0.f;
        #pragma unroll
        for (int q = 0; q < 32; q += 2) {
            s0 += sX[go + 32 + i][go + 32 + q]     * sT[g * 32 + q][j];
            s1 += sX[go + 32 + i][go + 32 + q + 1] * sT[g * 32 + q + 1][j];
        }
        sX[go + 32 + i][go + j] = -(s0 + s1);
    }
    __syncthreads();

    {
        float acc[4][4];
        #pragma unroll
        for (int u = 0; u < 4; u++)
            #pragma unroll
            for (int v = 0; v < 4; v++) acc[u][v] = 0.f;
        for (int q = 0; q < 64; q++) {
            float a4[4], b4[4];
            #pragma unroll
            for (int u = 0; u < 4; u++) a4[u] = sA[64 + tr * 4 + u][q];
            #pragma unroll
            for (int v = 0; v < 4; v++) b4[v] = sX[q][tc * 4 + v];
            #pragma unroll
            for (int u = 0; u < 4; u++)
                #pragma unroll
                for (int v = 0; v < 4; v++)
                    acc[u][v] += a4[u] * b4[v];
        }
        #pragma unroll
        for (int u = 0; u < 4; u++)
            #pragma unroll
            for (int v = 0; v < 4; v++)
                sT[tr * 4 + u][tc * 4 + v] = acc[u][v];
        __syncthreads();
        float ac2[4][4];
        #pragma unroll
        for (int u = 0; u < 4; u++)
            #pragma unroll
            for (int v = 0; v < 4; v++) ac2[u][v] = 0.f;
        for (int q = 0; q < 64; q++) {
            float a4[4], b4[4];
            #pragma unroll
            for (int u = 0; u < 4; u++) a4[u] = sX[64 + tr * 4 + u][64 + q];
            #pragma unroll
            for (int v = 0; v < 4; v++) b4[v] = sT[q][tc * 4 + v];
            #pragma unroll
            for (int u = 0; u < 4; u++)
                #pragma unroll
                for (int v = 0; v < 4; v++)
                    ac2[u][v] += a4[u] * b4[v];
        }
        #pragma unroll
        for (int u = 0; u < 4; u++)
            #pragma unroll
            for (int v = 0; v < 4; v++)
                sX[64 + tr * 4 + u][tc * 4 + v] = -ac2[u][v];
        __syncthreads();
    }

    #pragma unroll 4
    for (int i = 0; i < 64; i++) {
        int e = t + i * 256;
        int r = e >> 7, c = e & 127;
        g_invL[b][r * 128 + c] = sX[r][c];
    }
}

// ---------------- panel step as GEMM (float4 loads): L21 = A21*invL^T ; z'=invL*Z_k --
__global__ void __launch_bounds__(256, 2)
panel_gemm(int k)
{
    extern __shared__ float dsm[];
    float* As = dsm;                 // [2][16][UPAD]
    float* Bs = dsm + 2 * 16 * UPAD;
    int b = blockIdx.y;
    int mrem = NSTEP - 1 - k;
    int bi = blockIdx.x;
    bool isP = bi < mrem;
    int off = k * NB;
    float* Lb = g_Lf[b];
    float* Zb = g_Z[b];
    const float* IL = g_invL[b];
    int tid = threadIdx.x;
    int tr = tid >> 4, tc = tid & 15;
    int rowbase = off + NB + bi * 128;
    int zcolbase = (bi - mrem) * 128;

    int m4 = tid >> 2, kq = (tid & 3) * 4;
    int kz4 = tid >> 5, nq = (tid & 31) * 4;

    float acc[8][8];
    #pragma unroll
    for (int u = 0; u < 8; u++)
        #pragma unroll
        for (int v = 0; v < 8; v++) acc[u][v] = 0.f;

    float4 va[2], vb[2];
    #pragma unroll
    for (int i = 0; i < 2; i++) {
        int m = m4 + i * 64;
        if (isP) {
            va[i] = *(const float4*)&Lb[(long)(rowbase + m) * NN + off + kq];
            vb[i] = *(const float4*)&IL[m * 128 + kq];
        } else {
            va[i] = *(const float4*)&IL[m * 128 + kq];
            int kz = kz4 + i * 8;
            vb[i] = *(const float4*)&Zb[(long)(off + kz) * LDZ + zcolbase + nq];
        }
    }
    #pragma unroll
    for (int i = 0; i < 2; i++) {
        int m = m4 + i * 64;
        As[(kq + 0) * UPAD + m] = va[i].x;
        As[(kq + 1) * UPAD + m] = va[i].y;
        As[(kq + 2) * UPAD + m] = va[i].z;
        As[(kq + 3) * UPAD + m] = va[i].w;
        if (isP) {
            Bs[(kq + 0) * UPAD + m] = vb[i].x;
            Bs[(kq + 1) * UPAD + m] = vb[i].y;
            Bs[(kq + 2) * UPAD + m] = vb[i].z;
            Bs[(kq + 3) * UPAD + m] = vb[i].w;
        } else {
            int kz = kz4 + i * 8;
            *(float4*)&Bs[kz * UPAD + nq] = vb[i];
        }
    }
    __syncthreads();

    for (int it = 0; it < 8; it++) {
        int p = it & 1;
        if (it + 1 < 8) {
            int k0 = (it + 1) * 16;
            #pragma unroll
            for (int i = 0; i < 2; i++) {
                int m = m4 + i * 64;
                if (isP) {
                    va[i] = *(const float4*)&Lb[(long)(rowbase + m) * NN + off + k0 + kq];
                    vb[i] = *(const float4*)&IL[m * 128 + k0 + kq];
                } else {
                    va[i] = *(const float4*)&IL[m * 128 + k0 + kq];
                    int kz = kz4 + i * 8;
                    vb[i] = *(const float4*)&Zb[(long)(off + k0 + kz) * LDZ + zcolbase + nq];
                }
            }
        }
        float* Ap = As + p * 16 * UPAD;
        float* Bp = Bs + p * 16 * UPAD;
        #pragma unroll
        for (int kk = 0; kk < 16; kk++) {
            float a[8], bb[8];
            *reinterpret_cast<float4*>(&a[0])  = *reinterpret_cast<float4*>(Ap + kk * UPAD + tr * 4);
            *reinterpret_cast<float4*>(&a[4])  = *reinterpret_cast<float4*>(Ap + kk * UPAD + 64 + tr * 4);
            *reinterpret_cast<float4*>(&bb[0]) = *reinterpret_cast<float4*>(Bp + kk * UPAD + tc * 4);
            *reinterpret_cast<float4*>(&bb[4]) = *reinterpret_cast<float4*>(Bp + kk * UPAD + 64 + tc * 4);
            #pragma unroll
            for (int u = 0; u < 8; u++)
                #pragma unroll
                for (int v = 0; v < 8; v++)
                    acc[u][v] += a[u] * bb[v];
        }
        if (it + 1 < 8) {
            int q = (it + 1) & 1;
            float* Aq = As + q * 16 * UPAD;
            float* Bq = Bs + q * 16 * UPAD;
            #pragma unroll
            for (int i = 0; i < 2; i++) {
                int m = m4 + i * 64;
                Aq[(kq + 0) * UPAD + m] = va[i].x;
                Aq[(kq + 1) * UPAD + m] = va[i].y;
                Aq[(kq + 2) * UPAD + m] = va[i].z;
                Aq[(kq + 3) * UPAD + m] = va[i].w;
                if (isP) {
                    Bq[(kq + 0) * UPAD + m] = vb[i].x;
                    Bq[(kq + 1) * UPAD + m] = vb[i].y;
                    Bq[(kq + 2) * UPAD + m] = vb[i].z;
                    Bq[(kq + 3) * UPAD + m] = vb[i].w;
                } else {
                    int kz = kz4 + i * 8;
                    *(float4*)&Bq[kz * UPAD + nq] = vb[i];
                }
            }
        }
        __syncthreads();
    }

    #pragma unroll
    for (int u = 0; u < 8; u++) {
        int row = ((u < 4) ? tr * 4 + u : 64 + tr * 4 + (u - 4));
        #pragma unroll
        for (int v = 0; v < 8; v++) {
            int n = ((v < 4) ? tc * 4 + v : 64 + tc * 4 + (v - 4));
            if (isP) {
                Lb[(long)(rowbase + row) * NN + off + n] = acc[u][v];
            } else {
                int col = zcolbase + n;
                if (col < NRHS)
                    Zb[(long)(off + row) * LDZ + col] = acc[u][v];
            }
        }
    }
}

// ---------------- trailing update (float4 loads); tile (0,0) always skipped ----
__global__ void __launch_bounds__(256, 2)
ustep(int k)
{
    extern __shared__ float dsm[];
    float* As = dsm;
    float* Bs = dsm + 2 * 16 * UPAD;
    int b = blockIdx.z;
    int mrem = NSTEP - 1 - k;
    int mt = mrem;
    int bi = blockIdx.x, bj = blockIdx.y;
    bool isA = bj < mt;
    if (isA && bj > bi) return;
    if (isA && bi == 0 && bj == 0) return;   // diag(k+1) applies this update itself
    int rowoff = (k + 1) * NB;
    float* Lb = g_Lf[b];
    float* Zb = g_Z[b];
    int tid = threadIdx.x;
    int tr = tid >> 4, tc = tid & 15;
    int zcolbase = (bj - mt) * 128;

    int m4 = tid >> 2, kq = (tid & 3) * 4;
    int kz4 = tid >> 5, nq = (tid & 31) * 4;

    float acc[8][8];
    #pragma unroll
    for (int u = 0; u < 8; u++)
        #pragma unroll
        for (int v = 0; v < 8; v++) acc[u][v] = 0.f;

    const long arow = (long)(rowoff + bi * 128) * NN + k * NB;
    const long brow = isA ? (long)(rowoff + bj * 128) * NN + k * NB : 0;

    float4 va[2], vb[2];
    #pragma unroll
    for (int i = 0; i < 2; i++) {
        int m = m4 + i * 64;
        va[i] = *(const float4*)&Lb[arow + (long)m * NN + kq];
        if (isA) vb[i] = *(const float4*)&Lb[brow + (long)m * NN + kq];
        else {
            int kz = kz4 + i * 8;
            vb[i] = *(const float4*)&Zb[(long)(k * NB + kz) * LDZ + zcolbase + nq];
        }
    }
    #pragma unroll
    for (int i = 0; i < 2; i++) {
        int m = m4 + i * 64;
        As[(kq + 0) * UPAD + m] = va[i].x;
        As[(kq + 1) * UPAD + m] = va[i].y;
        As[(kq + 2) * UPAD + m] = va[i].z;
        As[(kq + 3) * UPAD + m] = va[i].w;
        if (isA) {
            Bs[(kq + 0) * UPAD + m] = vb[i].x;
            Bs[(kq + 1) * UPAD + m] = vb[i].y;
            Bs[(kq + 2) * UPAD + m] = vb[i].z;
            Bs[(kq + 3) * UPAD + m] = vb[i].w;
        } else {
            int kz = kz4 + i * 8;
            *(float4*)&Bs[kz * UPAD + nq] = vb[i];
        }
    }
    __syncthreads();

    for (int it = 0; it < 8; it++) {
        int p = it & 1;
        if (it + 1 < 8) {
            int k0 = (it + 1) * 16;
            #pragma unroll
            for (int i = 0; i < 2; i++) {
                int m = m4 + i * 64;
                va[i] = *(const float4*)&Lb[arow + (long)m * NN + k0 + kq];
                if (isA) vb[i] = *(const float4*)&Lb[brow + (long)m * NN + k0 + kq];
                else {
                    int kz = kz4 + i * 8;
                    vb[i] = *(const float4*)&Zb[(long)(k * NB + k0 + kz) * LDZ + zcolbase + nq];
                }
            }
        }
        float* Ap = As + p * 16 * UPAD;
        float* Bp = Bs + p * 16 * UPAD;
        #pragma unroll
        for (int kk = 0; kk < 16; kk++) {
            float a[8], bb[8];
            *reinterpret_cast<float4*>(&a[0])  = *reinterpret_cast<float4*>(Ap + kk * UPAD + tr * 4);
            *reinterpret_cast<float4*>(&a[4])  = *reinterpret_cast<float4*>(Ap + kk * UPAD + 64 + tr * 4);
            *reinterpret_cast<float4*>(&bb[0]) = *reinterpret_cast<float4*>(Bp + kk * UPAD + tc * 4);
            *reinterpret_cast<float4*>(&bb[4]) = *reinterpret_cast<float4*>(Bp + kk * UPAD + 64 + tc * 4);
            #pragma unroll
            for (int u = 0; u < 8; u++)
                #pragma unroll
                for (int v = 0; v < 8; v++)
                    acc[u][v] += a[u] * bb[v];
        }
        if (it + 1 < 8) {
            int q = (it + 1) & 1;
            float* Aq = As + q * 16 * UPAD;
            float* Bq = Bs + q * 16 * UPAD;
            #pragma unroll
            for (int i = 0; i < 2; i++) {
                int m = m4 + i * 64;
                Aq[(kq + 0) * UPAD + m] = va[i].x;
                Aq[(kq + 1) * UPAD + m] = va[i].y;
                Aq[(kq + 2) * UPAD + m] = va[i].z;
                Aq[(kq + 3) * UPAD + m] = va[i].w;
                if (isA) {
                    Bq[(kq + 0) * UPAD + m] = vb[i].x;
                    Bq[(kq + 1) * UPAD + m] = vb[i].y;
                    Bq[(kq + 2) * UPAD + m] = vb[i].z;
                    Bq[(kq + 3) * UPAD + m] = vb[i].w;
                } else {
                    int kz = kz4 + i * 8;
                    *(float4*)&Bq[kz * UPAD + nq] = vb[i];
                }
            }
        }
        __syncthreads();
    }

    #pragma unroll
    for (int u = 0; u < 8; u++) {
        int row = bi * 128 + ((u < 4) ? tr * 4 + u : 64 + tr * 4 + (u - 4));
        #pragma unroll
        for (int v = 0; v < 8; v++) {
            int n = ((v < 4) ? tc * 4 + v : 64 + tc * 4 + (v - 4));
            if (isA) {
                int col = bj * 128 + n;
                Lb[(long)(rowoff + row) * NN + rowoff + col] -= acc[u][v];
            } else {
                int col = zcolbase + n;
                if (col < NRHS)
                    Zb[(long)(rowoff + row) * LDZ + col] -= acc[u][v];
            }
        }
    }
}

// ---------------- W = T^T T (batched syrk, float4 loads, K-split x2) ----------
__global__ void __launch_bounds__(256, 2)
syrk_W()
{
    extern __shared__ float dsm[];
    float* As = dsm;
    float* Bs = dsm + 2 * 16 * UPAD;
    int bi = blockIdx.x, bj = blockIdx.y;
    int zz = blockIdx.z;
    int b = zz & 3, half = zz >> 2;
    if (bj > bi) return;
    const float* Zb = g_Z[b];
    float* Wb = half ? g_W2[b] : g_W[b];
    int kbase = half * 32;
    int tid = threadIdx.x;
    int tr = tid >> 4, tc = tid & 15;
    int kk4 = tid >> 5, mq = (tid & 31) * 4;

    float acc[8][8];
    #pragma unroll
    for (int u = 0; u < 8; u++)
        #pragma unroll
        for (int v = 0; v < 8; v++) acc[u][v] = 0.f;

    float4 va[2], vb[2];
    #pragma unroll
    for (int i = 0; i < 2; i++) {
        int kk = kk4 + i * 8;
        va[i] = *(const float4*)&Zb[(long)(kbase * 16 + kk) * LDZ + bi * 128 + mq];
        vb[i] = *(const float4*)&Zb[(long)(kbase * 16 + kk) * LDZ + bj * 128 + mq];
    }
    #pragma unroll
    for (int i = 0; i < 2; i++) {
        int kk = kk4 + i * 8;
        *(float4*)&As[kk * UPAD + mq] = va[i];
        *(float4*)&Bs[kk * UPAD + mq] = vb[i];
    }
    __syncthreads();

    for (int it = 0; it < 32; it++) {
        int p = it & 1;
        if (it + 1 < 32) {
            int k0 = (kbase + it + 1) * 16;
            #pragma unroll
            for (int i = 0; i < 2; i++) {
                int kk = kk4 + i * 8;
                va[i] = *(const float4*)&Zb[(long)(k0 + kk) * LDZ + bi * 128 + mq];
                vb[i] = *(const float4*)&Zb[(long)(k0 + kk) * LDZ + bj * 128 + mq];
            }
        }
        float* Ap = As + p * 16 * UPAD;
        float* Bp = Bs + p * 16 * UPAD;
        #pragma unroll
        for (int kk = 0; kk < 16; kk++) {
            float a[8], bb[8];
            *reinterpret_cast<float4*>(&a[0])  = *reinterpret_cast<float4*>(Ap + kk * UPAD + tr * 4);
            *reinterpret_cast<float4*>(&a[4])  = *reinterpret_cast<float4*>(Ap + kk * UPAD + 64 + tr * 4);
            *reinterpret_cast<float4*>(&bb[0]) = *reinterpret_cast<float4*>(Bp + kk * UPAD + tc * 4);
            *reinterpret_cast<float4*>(&bb[4]) = *reinterpret_cast<float4*>(Bp + kk * UPAD + 64 + tc * 4);
            #pragma unroll
            for (int u = 0; u < 8; u++)
                #pragma unroll
                for (int v = 0; v < 8; v++)
                    acc[u][v] += a[u] * bb[v];
        }
        if (it + 1 < 32) {
            int q = (it + 1) & 1;
            float* Aq = As + q * 16 * UPAD;
            float* Bq = Bs + q * 16 * UPAD;
            #pragma unroll
            for (int i = 0; i < 2; i++) {
                int kk = kk4 + i * 8;
                *(float4*)&Aq[kk * UPAD + mq] = va[i];
                *(float4*)&Bq[kk * UPAD + mq] = vb[i];
            }
        }
        __syncthreads();
    }

    #pragma unroll
    for (int u = 0; u < 8; u++) {
        int row = bi * 128 + ((u < 4) ? tr * 4 + u : 64 + tr * 4 + (u - 4));
        #pragma unroll
        for (int v = 0; v < 8; v++) {
            int col = bj * 128 + ((v < 4) ? tc * 4 + v : 64 + tc * 4 + (v - 4));
            float o = acc[u][v];
            Wb[(long)row * NN + col] = o;
            if (bi != bj) Wb[(long)col * NN + row] = o;
        }
    }
}

// ---------------- fmean: Fp_b[m] = sum_n T_b[n][m] * u_b[n] ----------------
__global__ void fmean_dot()
{
    int b = blockIdx.y;
    int m = blockIdx.x * 256 + threadIdx.x;
    __shared__ float su[NN];
    const float* Zb = g_Z[b];
    for (int n = threadIdx.x; n < NN; n += 256) su[n] = Zb[(long)n * LDZ + NN];
    __syncthreads();
    float a0 = 0.f, a1 = 0.f, a2 = 0.f, a3 = 0.f;
    #pragma unroll 4
    for (int n = 0; n < NN; n += 4) {
        a0 += Zb[(long)n * LDZ + m]       * su[n];
        a1 += Zb[(long)(n + 1) * LDZ + m] * su[n + 1];
        a2 += Zb[(long)(n + 2) * LDZ + m] * su[n + 2];
        a3 += Zb[(long)(n + 3) * LDZ + m] * su[n + 3];
    }
    g_Fp[b][m] = (a0 + a1) + (a2 + a3);
}

__global__ void fmean_comb(float* __restrict__ out)
{
    int m = blockIdx.x * 256 + threadIdx.x;
    if (m >= NN) return;
    float f0 = g_Fp[0][m], f1 = g_Fp[1][m], f2 = g_Fp[2][m], f3 = g_Fp[3][m];
    #pragma unroll
    for (int q = 0; q < LLt; q++) {
        float v = f0 * g_sm.G[0][q] + f1 * g_sm.G[1][q]
                + f2 * g_sm.G[2][q] + f3 * g_sm.G[3][q];
        out[(long)q * NN + m] = v;
        out[4096L + 2L * 16777216L + (long)m * 4 + q] = v;
    }
}

// ---------------- fvar assembly (sums the two K-half W partials) --------------
__global__ void fvar_kernel(float* __restrict__ out)
{
    int idx = blockIdx.x * 256 + threadIdx.x;
    int a  = idx >> 8;
    int b4 = idx & 255;
    long vi = (long)a * 256 + b4;
    float4 vt = reinterpret_cast<const float4*>(g_Ctt)[vi];
    float4 w0 = reinterpret_cast<const float4*>(g_W[0])[vi];
    float4 w1 = reinterpret_cast<const float4*>(g_W[1])[vi];
    float4 w2 = reinterpret_cast<const float4*>(g_W[2])[vi];
    float4 w3 = reinterpret_cast<const float4*>(g_W[3])[vi];
    float4 x0 = reinterpret_cast<const float4*>(g_W2[0])[vi];
    float4 x1 = reinterpret_cast<const float4*>(g_W2[1])[vi];
    float4 x2 = reinterpret_cast<const float4*>(g_W2[2])[vi];
    float4 x3 = reinterpret_cast<const float4*>(g_W2[3])[vi];
    w0.x += x0.x; w0.y += x0.y; w0.z += x0.z; w0.w += x0.w;
    w1.x += x1.x; w1.y += x1.y; w1.z += x1.z; w1.w += x1.w;
    w2.x += x2.x; w2.y += x2.y; w2.z += x2.z; w2.w += x2.w;
    w3.x += x3.x; w3.y += x3.y; w3.z += x3.z; w3.w += x3.w;
    float4* fv = reinterpret_cast<float4*>(out + 4096);
    #pragma unroll
    for (int q = 0; q < 4; q++) {
        #pragma unroll
        for (int r = 0; r < 4; r++) {
            float cb = g_sm.B[q][r];
            float c0 = g_sm.G[0][q] * g_sm.G[0][r];
            float c1 = g_sm.G[1][q] * g_sm.G[1][r];
            float c2 = g_sm.G[2][q] * g_sm.G[2][r];
            float c3 = g_sm.G[3][q] * g_sm.G[3][r];
            float4 v;
            v.x = cb * vt.x - c0 * w0.x - c1 * w1.x - c2 * w2.x - c3 * w3.x;
            v.y = cb * vt.y - c0 * w0.y - c1 * w1.y - c2 * w2.y - c3 * w3.y;
            v.z = cb * vt.z - c0 * w0.z - c1 * w1.z - c2 * w2.z - c3 * w3.z;
            v.w = cb * vt.w - c0 * w0.w - c1 * w1.w - c2 * w2.w - c3 * w3.w;
            fv[(long)(q * NN + a) * 1024 + r * 256 + b4] = v;
        }
    }
}

// ---------------- noise output (zeros + diagonal in one pass) ----------------
__global__ void noise_fill(float* __restrict__ out)
{
    long i = (long)blockIdx.x * 256 + threadIdx.x;
    long base = i * 4;
    int row = (int)(base >> 12);
    int col0 = (int)(base & 4095);
    float4 v = make_float4(0.f, 0.f, 0.f, 0.f);
    if (row >= col0 && row < col0 + 4)
        reinterpret_cast<float*>(&v)[row - col0] = g_sm.dn[row >> 10];
    reinterpret_cast<float4*>(out + 4096 + 16777216L)[i] = v;
}

// ---------------- launcher (single extra stream: diag(k+1) || ustep(k)) --------
extern "C" void kernel_launch(void* const* d_in, const int* in_sizes, int n_in,
                              void* d_out, int out_size)
{
    const float* X      = (const float*)d_in[0];
    const float* tX     = (const float*)d_in[1];
    const float* Y      = (const float*)d_in[2];
    const float* lnoise = (const float*)d_in[3];
    const float* cf     = (const float*)d_in[4];
    const float* lvar   = (const float*)d_in[5];
    const float* lls    = (const float*)d_in[6];
    float* out = (float*)d_out;
    int l = in_sizes[3];
    int rank = in_sizes[4] / l;
    (void)l;

    const int DSMEM = (2 * 128 * 129 + 64 * 65 + 128) * 4;   // 149248 B
    const int GSMEM = 2 * 2 * 16 * UPAD * 4;                 // 67584 B
    cudaFuncSetAttribute(diag_step,  cudaFuncAttributeMaxDynamicSharedMemorySize, DSMEM);
    cudaFuncSetAttribute(panel_gemm, cudaFuncAttributeMaxDynamicSharedMemorySize, GSMEM);
    cudaFuncSetAttribute(ustep,      cudaFuncAttributeMaxDynamicSharedMemorySize, GSMEM);
    cudaFuncSetAttribute(syrk_W,     cudaFuncAttributeMaxDynamicSharedMemorySize, GSMEM);

    cudaStream_t s2;
    cudaStreamCreateWithFlags(&s2, cudaStreamNonBlocking);
    cudaEvent_t evA, evB;
    cudaEventCreateWithFlags(&evA, cudaEventDisableTiming);
    cudaEventCreateWithFlags(&evB, cudaEventDisableTiming);

    small_setup<<<1, 32>>>(lnoise, cf, lvar, lls, rank);
    rbf_all<<<NN * NN / 256, 256>>>(X, tX, Y);
    noise_fill<<<16384, 256>>>(out);
    diag_step<<<LLt, 256, DSMEM>>>(0);

    // factor + forward-solve sweep; diag(k+1) depends only on panel(k),
    // overlaps the entire ustep(k) on s2.
    for (int k = 0; k < NSTEP; k++) {
        int mrem = NSTEP - 1 - k;
        panel_gemm<<<dim3(mrem + 9, LLt), 256, GSMEM>>>(k);
        if (mrem > 0) {
            cudaEventRecord(evA, 0);
            cudaStreamWaitEvent(s2, evA, 0);
            diag_step<<<LLt, 256, DSMEM, s2>>>(k + 1);               // self-contained
            cudaEventRecord(evB, s2);
            ustep<<<dim3(mrem, mrem + 9, LLt), 256, GSMEM>>>(k);     // skips tile (0,0)
            cudaStreamWaitEvent(0, evB, 0);
        }
    }

    // W_i = T_i^T T_i  (batched syrk, K-split x2: 288 working CTAs)
    syrk_W<<<dim3(8, 8, LLt * 2), 256, GSMEM>>>();

    // fmean = sum_i G[i][q] * T_i^T u_i
    fmean_dot<<<dim3(4, LLt), 256>>>();
    fmean_comb<<<4, 256>>>(out);

    // fvar and noise outputs
    fvar_kernel<<<1024, 256>>>(out);
}

// round 17
// speedup vs baseline: 1.2378x; 1.0357x over previous
#include <cuda_runtime.h>
#include <math.h>

#define NN 1024           // N = N_ = 1024 training/test points
#define LLt 4             // l = 4 tasks
#define DD 8              // input dim
#define NB 128            // factorization block size
#define NSTEP 8           // NN / NB
#define LDZ 1152          // padded leading dim for Z (9 full 128-col tiles)
#define NRHS 1025         // 1024 Cx columns + 1 ytil column
#define UPAD 132          // smem tile row padding for gemm kernels

// ---------------- device scratch (static: no allocation allowed) ----------------
__device__ float g_Ctt[NN * NN];        // rbf(test_X, test_X)
__device__ float g_Lf[LLt][NN * NN];    // per-batch A_i = s_i*C + I -> L panels in-place
__device__ float g_Z[LLt][NN * LDZ];    // per-batch RHS [Cx | ytil_i]; cols >= NRHS stay 0
__device__ float g_W[LLt][NN * NN];     // W_i partial (K half 0)
__device__ float g_W2[LLt][NN * NN];    // W_i partial (K half 1)
__device__ float g_Fp[LLt][NN];         // per-batch T_i^T u_i
__device__ float g_invL[LLt][NB * NB];  // per-step inverse of diag block

struct Small {
    float s[LLt];          // eigenvalues of B'
    float G[LLt][LLt];     // G[i][q] = (U^T D^{-1/2} B)[i][q]
    float B[LLt][LLt];     // task_K
    float dn[LLt];         // exp(log_noise)
    float DU[LLt][LLt];    // DU[p][i] = dns[p]*U[p][i]
    float inv2ls2;         // 0.5 / ls^2
};
__device__ Small g_sm;

// ---------------- small setup: task matrix, 4x4 Jacobi eig ----------------
__global__ void small_setup(const float* __restrict__ log_noise,
                            const float* __restrict__ covar_factor,
                            const float* __restrict__ log_var,
                            const float* __restrict__ log_ls, int rank)
{
    if (threadIdx.x != 0 || blockIdx.x != 0) return;
    double dn[LLt], dns[LLt];
    for (int p = 0; p < LLt; p++) {
        dn[p]  = exp((double)log_noise[p]);
        dns[p] = exp(-0.5 * (double)log_noise[p]);
    }
    double B[LLt][LLt];
    for (int q = 0; q < LLt; q++)
        for (int r = 0; r < LLt; r++) {
            double s = 0.0;
            for (int k = 0; k < rank; k++)
                s += (double)covar_factor[q * rank + k] * (double)covar_factor[r * rank + k];
            if (q == r) s += exp((double)log_var[q]);
            B[q][r] = s;
        }
    double A[LLt][LLt], V[LLt][LLt];
    for (int q = 0; q < LLt; q++)
        for (int r = 0; r < LLt; r++) {
            A[q][r] = dns[q] * B[q][r] * dns[r];
            V[q][r] = (q == r) ? 1.0 : 0.0;
        }
    for (int sweep = 0; sweep < 40; sweep++) {
        for (int p = 0; p < LLt - 1; p++)
            for (int q = p + 1; q < LLt; q++) {
                double apq = A[p][q];
                if (fabs(apq) < 1e-300) continue;
                double theta = 0.5 * atan2(2.0 * apq, A[q][q] - A[p][p]);
                double c = cos(theta), s = sin(theta);
                for (int k = 0; k < LLt; k++) {
                    double akp = A[k][p], akq = A[k][q];
                    A[k][p] = c * akp - s * akq;
                    A[k][q] = s * akp + c * akq;
                }
                for (int k = 0; k < LLt; k++) {
                    double apk = A[p][k], aqk = A[q][k];
                    A[p][k] = c * apk - s * aqk;
                    A[q][k] = s * apk + c * aqk;
                }
                for (int k = 0; k < LLt; k++) {
                    double vkp = V[k][p], vkq = V[k][q];
                    V[k][p] = c * vkp - s * vkq;
                    V[k][q] = s * vkp + c * vkq;
                }
            }
    }
    for (int i = 0; i < LLt; i++) g_sm.s[i] = (float)A[i][i];
    for (int p = 0; p < LLt; p++)
        for (int i = 0; i < LLt; i++)
            g_sm.DU[p][i] = (float)(dns[p] * V[p][i]);
    for (int i = 0; i < LLt; i++)
        for (int q = 0; q < LLt; q++) {
            double s = 0.0;
            for (int p = 0; p < LLt; p++) s += V[p][i] * dns[p] * B[p][q];
            g_sm.G[i][q] = (float)s;
        }
    for (int q = 0; q < LLt; q++)
        for (int r = 0; r < LLt; r++) g_sm.B[q][r] = (float)B[q][r];
    for (int p = 0; p < LLt; p++) g_sm.dn[p] = (float)dn[p];
    g_sm.inv2ls2 = (float)(0.5 * exp(-2.0 * (double)log_ls[0]));
}

// ---------------- merged RBF: A_b, Z (Cx cols + ytil col), Ctt ----------------
__global__ void rbf_all(const float* __restrict__ X, const float* __restrict__ tX,
                        const float* __restrict__ Y)
{
    int idx = blockIdx.x * 256 + threadIdx.x;
    int i = idx >> 10, j = idx & 1023;
    float dAA = 0.f, dAx = 0.f, dtt = 0.f;
    #pragma unroll
    for (int d = 0; d < DD; d++) {
        float xi = X[i * DD + d], xj = X[j * DD + d];
        float ti = tX[i * DD + d], tj = tX[j * DD + d];
        float a = xi - xj; dAA += a * a;
        float b = xi - tj; dAx += b * b;
        float c = ti - tj; dtt += c * c;
    }
    float s2 = g_sm.inv2ls2;
    float vAA = expf(-dAA * s2);
    float vAx = expf(-dAx * s2);
    g_Ctt[idx] = expf(-dtt * s2);
    float diag = (i == j) ? 1.f : 0.f;
    long zoff = (long)i * LDZ + j;
    #pragma unroll
    for (int b = 0; b < LLt; b++) {
        g_Lf[b][idx] = g_sm.s[b] * vAA + diag;
        g_Z[b][zoff] = vAx;
    }
    if (idx < NN) {
        int n = idx;
        float y0 = Y[n * 4 + 0], y1 = Y[n * 4 + 1], y2 = Y[n * 4 + 2], y3 = Y[n * 4 + 3];
        #pragma unroll
        for (int b = 0; b < LLt; b++)
            g_Z[b][(long)n * LDZ + NN] = y0 * g_sm.DU[0][b] + y1 * g_sm.DU[1][b]
                                       + y2 * g_sm.DU[2][b] + y3 * g_sm.DU[3][b];
    }
}

// ---------------- P = A21 * inv32^T, then trailing -= P P^T. UR*16 = panel height ----
template<int UR>
__device__ __forceinline__ void panel_and_update(float (*sA)[129], float (*sI)[129],
                                                 int o, int tr, int tc)
{
    float pacc[UR][2];
    #pragma unroll
    for (int u = 0; u < UR; u++) { pacc[u][0] = 0.f; pacc[u][1] = 0.f; }
    #pragma unroll
    for (int q = 0; q < 32; q++) {
        float b0 = sI[o + tc][o + q];
        float b1 = sI[o + tc + 16][o + q];
        #pragma unroll
        for (int u = 0; u < UR; u++) {
            float a = sA[o + 32 + tr + 16 * u][o + q];
            pacc[u][0] += a * b0;
            pacc[u][1] += a * b1;
        }
    }
    __syncthreads();
    #pragma unroll
    for (int u = 0; u < UR; u++) {
        sA[o + 32 + tr + 16 * u][o + tc]      = pacc[u][0];
        sA[o + 32 + tr + 16 * u][o + tc + 16] = pacc[u][1];
    }
    __syncthreads();
    float upd[UR][UR];
    #pragma unroll
    for (int u = 0; u < UR; u++)
        #pragma unroll
        for (int v = 0; v < UR; v++) upd[u][v] = 0.f;
    #pragma unroll
    for (int q = 0; q < 32; q++) {
        float av[UR], bv[UR];
        #pragma unroll
        for (int u = 0; u < UR; u++) av[u] = sA[o + 32 + tr + 16 * u][o + q];
        #pragma unroll
        for (int v = 0; v < UR; v++) bv[v] = sA[o + 32 + tc + 16 * v][o + q];
        #pragma unroll
        for (int u = 0; u < UR; u++)
            #pragma unroll
            for (int v = 0; v < UR; v++)
                upd[u][v] += av[u] * bv[v];
    }
    #pragma unroll
    for (int u = 0; u < UR; u++)
        #pragma unroll
        for (int v = 0; v < UR; v++)
            sA[o + 32 + tr + 16 * u][o + 32 + tc + 16 * v] -= upd[u][v];
}

// ---------------- diag step: self-contained (applies own rank-128 update) ------
__global__ void __launch_bounds__(256)
diag_step(int k)
{
    extern __shared__ float dsm[];
    float (*sA)[129] = (float(*)[129])dsm;                    // 128x129 : A -> L
    float (*sX)[129] = (float(*)[129])(dsm + 128 * 129);      // 128x129 : P, then invL
    float (*sT)[65]  = (float(*)[65])(dsm + 2 * 128 * 129);   // 64x65 scratch
    float* rd        = dsm + 2 * 128 * 129 + 64 * 65;         // 128 recip diag
    int b = blockIdx.x;
    int t = threadIdx.x;
    int lane = t & 31, warp = t >> 5;
    int tr = t >> 4, tc = t & 15;
    int off = k * NB;
    float* Lb = g_Lf[b];

    #pragma unroll 4
    for (int i = 0; i < 64; i++) {
        int e = t + i * 256;
        int r = e >> 7, c = e & 127;
        sA[r][c] = Lb[(long)(off + r) * NN + off + c];
        if (k > 0) sX[r][c] = Lb[(long)(off + r) * NN + (off - NB) + c];
    }
    __syncthreads();

    if (k > 0) {
        float acc[8][8];
        #pragma unroll
        for (int u = 0; u < 8; u++)
            #pragma unroll
            for (int v = 0; v < 8; v++) acc[u][v] = 0.f;
        for (int q = 0; q < 128; q++) {
            float a8[8], b8[8];
            #pragma unroll
            for (int u = 0; u < 8; u++) a8[u] = sX[tr * 8 + u][q];
            #pragma unroll
            for (int v = 0; v < 8; v++) b8[v] = sX[tc * 8 + v][q];
            #pragma unroll
            for (int u = 0; u < 8; u++)
                #pragma unroll
                for (int v = 0; v < 8; v++)
                    acc[u][v] += a8[u] * b8[v];
        }
        __syncthreads();
        #pragma unroll
        for (int u = 0; u < 8; u++)
            #pragma unroll
            for (int v = 0; v < 8; v++)
                sA[tr * 8 + u][tc * 8 + v] -= acc[u][v];
    }
    #pragma unroll 4
    for (int i = 0; i < 64; i++) {
        int e = t + i * 256;
        sX[e >> 7][e & 127] = 0.f;
    }
    __syncthreads();

    for (int p = 0; p < 4; p++) {
        int o = p * 32;
        if (warp == 0) {
            float r[32];
            #pragma unroll
            for (int kk = 0; kk < 32; kk++) r[kk] = sA[o + lane][o + kk];
            #pragma unroll
            for (int j = 0; j < 32; j++) {
                float dj = __shfl_sync(0xffffffffu, r[j], j);
                float invd = rsqrtf(dj);
                float Lj = r[j] * invd;
                sA[o + lane][o + j] = (lane >= j) ? Lj : 0.f;
                if (lane == j) rd[o + j] = invd;
                #pragma unroll
                for (int kk = j + 1; kk < 32; kk++) {
                    float Lkj = __shfl_sync(0xffffffffu, Lj, kk);
                    r[kk] -= Lj * Lkj;
                }
            }
            __syncwarp();
            {
                int c = lane;
                sX[o + c][o + c] = rd[o + c];
                #pragma unroll
                for (int j = 1; j < 32; j++) {
                    float s0 = 0.f, s1 = 0.f;
                    #pragma unroll
                    for (int kk = 0; kk < j; kk++) {
                        float v = sA[o + j][o + kk] * sX[o + kk][o + c];
                        if (kk & 1) s1 += v; else s0 += v;
                    }
                    if (j > c) sX[o + j][o + c] = -(s0 + s1) * rd[o + j];
                }
            }
            __syncwarp();
        }
        __syncthreads();
        if (p == 0)      panel_and_update<6>(sA, sX, o, tr, tc);
        else if (p == 1) panel_and_update<4>(sA, sX, o, tr, tc);
        else if (p == 2) panel_and_update<2>(sA, sX, o, tr, tc);
        __syncthreads();
    }

    #pragma unroll 2
    for (int e = t; e < 2048; e += 256) {
        int g = e >> 10, i = (e >> 5) & 31, j = e & 31;
        int go = g * 64;
        float s0 = 0.f, s1 = 0.f;
        #pragma unroll
        for (int q = 0; q < 32; q += 2) {
            s0 += sA[go + 32 + i][go + q]     * sX[go + q][go + j];
            s1 += sA[go + 32 + i][go + q + 1] * sX[go + q + 1][go + j];
        }
        sT[g * 32 + i][j] = s0 + s1;
    }
    __syncthreads();
    #pragma unroll 2
    for (int e = t; e < 2048; e += 256) {
        int g = e >> 10, i = (e >> 5) & 31, j = e & 31;
        int go = g * 64;
        float s0 = 0.f, s1 = 0.f;
        #pragma unroll
        for (int q = 0; q < 32; q += 2) {
            s0 += sX[go + 32 + i][go + 32 + q]     * sT[g * 32 + q][j];
            s1 += sX[go + 32 + i][go + 32 + q + 1] * sT[g * 32 + q + 1][j];
        }
        sX[go + 32 + i][go + j] = -(s0 + s1);
    }
    __syncthreads();

    {
        float acc[4][4];
        #pragma unroll
        for (int u = 0; u < 4; u++)
            #pragma unroll
            for (int v = 0; v < 4; v++) acc[u][v] = 0.f;
        for (int q = 0; q < 64; q++) {
            float a4[4], b4[4];
            #pragma unroll
            for (int u = 0; u < 4; u++) a4[u] = sA[64 + tr * 4 + u][q];
            #pragma unroll
            for (int v = 0; v < 4; v++) b4[v] = sX[q][tc * 4 + v];
            #pragma unroll
            for (int u = 0; u < 4; u++)
                #pragma unroll
                for (int v = 0; v < 4; v++)
                    acc[u][v] += a4[u] * b4[v];
        }
        #pragma unroll
        for (int u = 0; u < 4; u++)
            #pragma unroll
            for (int v = 0; v < 4; v++)
                sT[tr * 4 + u][tc * 4 + v] = acc[u][v];
        __syncthreads();
        float ac2[4][4];
        #pragma unroll
        for (int u = 0; u < 4; u++)
            #pragma unroll
            for (int v = 0; v < 4; v++) ac2[u][v] = 0.f;
        for (int q = 0; q < 64; q++) {
            float a4[4], b4[4];
            #pragma unroll
            for (int u = 0; u < 4; u++) a4[u] = sX[64 + tr * 4 + u][64 + q];
            #pragma unroll
            for (int v = 0; v < 4; v++) b4[v] = sT[q][tc * 4 + v];
            #pragma unroll
            for (int u = 0; u < 4; u++)
                #pragma unroll
                for (int v = 0; v < 4; v++)
                    ac2[u][v] += a4[u] * b4[v];
        }
        #pragma unroll
        for (int u = 0; u < 4; u++)
            #pragma unroll
            for (int v = 0; v < 4; v++)
                sX[64 + tr * 4 + u][tc * 4 + v] = -ac2[u][v];
        __syncthreads();
    }

    #pragma unroll 4
    for (int i = 0; i < 64; i++) {
        int e = t + i * 256;
        int r = e >> 7, c = e & 127;
        g_invL[b][r * 128 + c] = sX[r][c];
    }
}

// ---------------- panel step as GEMM (float4 loads): L21 = A21*invL^T ; z'=invL*Z_k --
__global__ void __launch_bounds__(256, 2)
panel_gemm(int k)
{
    extern __shared__ float dsm[];
    float* As = dsm;                 // [2][16][UPAD]
    float* Bs = dsm + 2 * 16 * UPAD;
    int b = blockIdx.y;
    int mrem = NSTEP - 1 - k;
    int bi = blockIdx.x;
    bool isP = bi < mrem;
    int off = k * NB;
    float* Lb = g_Lf[b];
    float* Zb = g_Z[b];
    const float* IL = g_invL[b];
    int tid = threadIdx.x;
    int tr = tid >> 4, tc = tid & 15;
    int rowbase = off + NB + bi * 128;
    int zcolbase = (bi - mrem) * 128;

    int m4 = tid >> 2, kq = (tid & 3) * 4;
    int kz4 = tid >> 5, nq = (tid & 31) * 4;

    float acc[8][8];
    #pragma unroll
    for (int u = 0; u < 8; u++)
        #pragma unroll
        for (int v = 0; v < 8; v++) acc[u][v] = 0.f;

    float4 va[2], vb[2];
    #pragma unroll
    for (int i = 0; i < 2; i++) {
        int m = m4 + i * 64;
        if (isP) {
            va[i] = *(const float4*)&Lb[(long)(rowbase + m) * NN + off + kq];
            vb[i] = *(const float4*)&IL[m * 128 + kq];
        } else {
            va[i] = *(const float4*)&IL[m * 128 + kq];
            int kz = kz4 + i * 8;
            vb[i] = *(const float4*)&Zb[(long)(off + kz) * LDZ + zcolbase + nq];
        }
    }
    #pragma unroll
    for (int i = 0; i < 2; i++) {
        int m = m4 + i * 64;
        As[(kq + 0) * UPAD + m] = va[i].x;
        As[(kq + 1) * UPAD + m] = va[i].y;
        As[(kq + 2) * UPAD + m] = va[i].z;
        As[(kq + 3) * UPAD + m] = va[i].w;
        if (isP) {
            Bs[(kq + 0) * UPAD + m] = vb[i].x;
            Bs[(kq + 1) * UPAD + m] = vb[i].y;
            Bs[(kq + 2) * UPAD + m] = vb[i].z;
            Bs[(kq + 3) * UPAD + m] = vb[i].w;
        } else {
            int kz = kz4 + i * 8;
            *(float4*)&Bs[kz * UPAD + nq] = vb[i];
        }
    }
    __syncthreads();

    for (int it = 0; it < 8; it++) {
        int p = it & 1;
        if (it + 1 < 8) {
            int k0 = (it + 1) * 16;
            #pragma unroll
            for (int i = 0; i < 2; i++) {
                int m = m4 + i * 64;
                if (isP) {
                    va[i] = *(const float4*)&Lb[(long)(rowbase + m) * NN + off + k0 + kq];
                    vb[i] = *(const float4*)&IL[m * 128 + k0 + kq];
                } else {
                    va[i] = *(const float4*)&IL[m * 128 + k0 + kq];
                    int kz = kz4 + i * 8;
                    vb[i] = *(const float4*)&Zb[(long)(off + k0 + kz) * LDZ + zcolbase + nq];
                }
            }
        }
        float* Ap = As + p * 16 * UPAD;
        float* Bp = Bs + p * 16 * UPAD;
        #pragma unroll
        for (int kk = 0; kk < 16; kk++) {
            float a[8], bb[8];
            *reinterpret_cast<float4*>(&a[0])  = *reinterpret_cast<float4*>(Ap + kk * UPAD + tr * 4);
            *reinterpret_cast<float4*>(&a[4])  = *reinterpret_cast<float4*>(Ap + kk * UPAD + 64 + tr * 4);
            *reinterpret_cast<float4*>(&bb[0]) = *reinterpret_cast<float4*>(Bp + kk * UPAD + tc * 4);
            *reinterpret_cast<float4*>(&bb[4]) = *reinterpret_cast<float4*>(Bp + kk * UPAD + 64 + tc * 4);
            #pragma unroll
            for (int u = 0; u < 8; u++)
                #pragma unroll
                for (int v = 0; v < 8; v++)
                    acc[u][v] += a[u] * bb[v];
        }
        if (it + 1 < 8) {
            int q = (it + 1) & 1;
            float* Aq = As + q * 16 * UPAD;
            float* Bq = Bs + q * 16 * UPAD;
            #pragma unroll
            for (int i = 0; i < 2; i++) {
                int m = m4 + i * 64;
                Aq[(kq + 0) * UPAD + m] = va[i].x;
                Aq[(kq + 1) * UPAD + m] = va[i].y;
                Aq[(kq + 2) * UPAD + m] = va[i].z;
                Aq[(kq + 3) * UPAD + m] = va[i].w;
                if (isP) {
                    Bq[(kq + 0) * UPAD + m] = vb[i].x;
                    Bq[(kq + 1) * UPAD + m] = vb[i].y;
                    Bq[(kq + 2) * UPAD + m] = vb[i].z;
                    Bq[(kq + 3) * UPAD + m] = vb[i].w;
                } else {
                    int kz = kz4 + i * 8;
                    *(float4*)&Bq[kz * UPAD + nq] = vb[i];
                }
            }
        }
        __syncthreads();
    }

    #pragma unroll
    for (int u = 0; u < 8; u++) {
        int row = ((u < 4) ? tr * 4 + u : 64 + tr * 4 + (u - 4));
        #pragma unroll
        for (int v = 0; v < 8; v++) {
            int n = ((v < 4) ? tc * 4 + v : 64 + tc * 4 + (v - 4));
            if (isP) {
                Lb[(long)(rowbase + row) * NN + off + n] = acc[u][v];
            } else {
                int col = zcolbase + n;
                if (col < NRHS)
                    Zb[(long)(off + row) * LDZ + col] = acc[u][v];
            }
        }
    }
}

// ---------------- trailing update (float4 loads); tile (0,0) always skipped ----
__global__ void __launch_bounds__(256, 2)
ustep(int k)
{
    extern __shared__ float dsm[];
    float* As = dsm;
    float* Bs = dsm + 2 * 16 * UPAD;
    int b = blockIdx.z;
    int mrem = NSTEP - 1 - k;
    int mt = mrem;
    int bi = blockIdx.x, bj = blockIdx.y;
    bool isA = bj < mt;
    if (isA && bj > bi) return;
    if (isA && bi == 0 && bj == 0) return;   // diag(k+1) applies this update itself
    int rowoff = (k + 1) * NB;
    float* Lb = g_Lf[b];
    float* Zb = g_Z[b];
    int tid = threadIdx.x;
    int tr = tid >> 4, tc = tid & 15;
    int zcolbase = (bj - mt) * 128;

    int m4 = tid >> 2, kq = (tid & 3) * 4;
    int kz4 = tid >> 5, nq = (tid & 31) * 4;

    float acc[8][8];
    #pragma unroll
    for (int u = 0; u < 8; u++)
        #pragma unroll
        for (int v = 0; v < 8; v++) acc[u][v] = 0.f;

    const long arow = (long)(rowoff + bi * 128) * NN + k * NB;
    const long brow = isA ? (long)(rowoff + bj * 128) * NN + k * NB : 0;

    float4 va[2], vb[2];
    #pragma unroll
    for (int i = 0; i < 2; i++) {
        int m = m4 + i * 64;
        va[i] = *(const float4*)&Lb[arow + (long)m * NN + kq];
        if (isA) vb[i] = *(const float4*)&Lb[brow + (long)m * NN + kq];
        else {
            int kz = kz4 + i * 8;
            vb[i] = *(const float4*)&Zb[(long)(k * NB + kz) * LDZ + zcolbase + nq];
        }
    }
    #pragma unroll
    for (int i = 0; i < 2; i++) {
        int m = m4 + i * 64;
        As[(kq + 0) * UPAD + m] = va[i].x;
        As[(kq + 1) * UPAD + m] = va[i].y;
        As[(kq + 2) * UPAD + m] = va[i].z;
        As[(kq + 3) * UPAD + m] = va[i].w;
        if (isA) {
            Bs[(kq + 0) * UPAD + m] = vb[i].x;
            Bs[(kq + 1) * UPAD + m] = vb[i].y;
            Bs[(kq + 2) * UPAD + m] = vb[i].z;
            Bs[(kq + 3) * UPAD + m] = vb[i].w;
        } else {
            int kz = kz4 + i * 8;
            *(float4*)&Bs[kz * UPAD + nq] = vb[i];
        }
    }
    __syncthreads();

    for (int it = 0; it < 8; it++) {
        int p = it & 1;
        if (it + 1 < 8) {
            int k0 = (it + 1) * 16;
            #pragma unroll
            for (int i = 0; i < 2; i++) {
                int m = m4 + i * 64;
                va[i] = *(const float4*)&Lb[arow + (long)m * NN + k0 + kq];
                if (isA) vb[i] = *(const float4*)&Lb[brow + (long)m * NN + k0 + kq];
                else {
                    int kz = kz4 + i * 8;
                    vb[i] = *(const float4*)&Zb[(long)(k * NB + k0 + kz) * LDZ + zcolbase + nq];
                }
            }
        }
        float* Ap = As + p * 16 * UPAD;
        float* Bp = Bs + p * 16 * UPAD;
        #pragma unroll
        for (int kk = 0; kk < 16; kk++) {
            float a[8], bb[8];
            *reinterpret_cast<float4*>(&a[0])  = *reinterpret_cast<float4*>(Ap + kk * UPAD + tr * 4);
            *reinterpret_cast<float4*>(&a[4])  = *reinterpret_cast<float4*>(Ap + kk * UPAD + 64 + tr * 4);
            *reinterpret_cast<float4*>(&bb[0]) = *reinterpret_cast<float4*>(Bp + kk * UPAD + tc * 4);
            *reinterpret_cast<float4*>(&bb[4]) = *reinterpret_cast<float4*>(Bp + kk * UPAD + 64 + tc * 4);
            #pragma unroll
            for (int u = 0; u < 8; u++)
                #pragma unroll
                for (int v = 0; v < 8; v++)
                    acc[u][v] += a[u] * bb[v];
        }
        if (it + 1 < 8) {
            int q = (it + 1) & 1;
            float* Aq = As + q * 16 * UPAD;
            float* Bq = Bs + q * 16 * UPAD;
            #pragma unroll
            for (int i = 0; i < 2; i++) {
                int m = m4 + i * 64;
                Aq[(kq + 0) * UPAD + m] = va[i].x;
                Aq[(kq + 1) * UPAD + m] = va[i].y;
                Aq[(kq + 2) * UPAD + m] = va[i].z;
                Aq[(kq + 3) * UPAD + m] = va[i].w;
                if (isA) {
                    Bq[(kq + 0) * UPAD + m] = vb[i].x;
                    Bq[(kq + 1) * UPAD + m] = vb[i].y;
                    Bq[(kq + 2) * UPAD + m] = vb[i].z;
                    Bq[(kq + 3) * UPAD + m] = vb[i].w;
                } else {
                    int kz = kz4 + i * 8;
                    *(float4*)&Bq[kz * UPAD + nq] = vb[i];
                }
            }
        }
        __syncthreads();
    }

    #pragma unroll
    for (int u = 0; u < 8; u++) {
        int row = bi * 128 + ((u < 4) ? tr * 4 + u : 64 + tr * 4 + (u - 4));
        #pragma unroll
        for (int v = 0; v < 8; v++) {
            int n = ((v < 4) ? tc * 4 + v : 64 + tc * 4 + (v - 4));
            if (isA) {
                int col = bj * 128 + n;
                Lb[(long)(rowoff + row) * NN + rowoff + col] -= acc[u][v];
            } else {
                int col = zcolbase + n;
                if (col < NRHS)
                    Zb[(long)(rowoff + row) * LDZ + col] -= acc[u][v];
            }
        }
    }
}

// ---------------- W = T^T T (batched syrk, float4 loads, K-split x2) ----------
__global__ void __launch_bounds__(256, 2)
syrk_W()
{
    extern __shared__ float dsm[];
    float* As = dsm;
    float* Bs = dsm + 2 * 16 * UPAD;
    int bi = blockIdx.x, bj = blockIdx.y;
    int zz = blockIdx.z;
    int b = zz & 3, half = zz >> 2;
    if (bj > bi) return;
    const float* Zb = g_Z[b];
    float* Wb = half ? g_W2[b] : g_W[b];
    int kbase = half * 32;
    int tid = threadIdx.x;
    int tr = tid >> 4, tc = tid & 15;
    int kk4 = tid >> 5, mq = (tid & 31) * 4;

    float acc[8][8];
    #pragma unroll
    for (int u = 0; u < 8; u++)
        #pragma unroll
        for (int v = 0; v < 8; v++) acc[u][v] = 0.f;

    float4 va[2], vb[2];
    #pragma unroll
    for (int i = 0; i < 2; i++) {
        int kk = kk4 + i * 8;
        va[i] = *(const float4*)&Zb[(long)(kbase * 16 + kk) * LDZ + bi * 128 + mq];
        vb[i] = *(const float4*)&Zb[(long)(kbase * 16 + kk) * LDZ + bj * 128 + mq];
    }
    #pragma unroll
    for (int i = 0; i < 2; i++) {
        int kk = kk4 + i * 8;
        *(float4*)&As[kk * UPAD + mq] = va[i];
        *(float4*)&Bs[kk * UPAD + mq] = vb[i];
    }
    __syncthreads();

    for (int it = 0; it < 32; it++) {
        int p = it & 1;
        if (it + 1 < 32) {
            int k0 = (kbase + it + 1) * 16;
            #pragma unroll
            for (int i = 0; i < 2; i++) {
                int kk = kk4 + i * 8;
                va[i] = *(const float4*)&Zb[(long)(k0 + kk) * LDZ + bi * 128 + mq];
                vb[i] = *(const float4*)&Zb[(long)(k0 + kk) * LDZ + bj * 128 + mq];
            }
        }
        float* Ap = As + p * 16 * UPAD;
        float* Bp = Bs + p * 16 * UPAD;
        #pragma unroll
        for (int kk = 0; kk < 16; kk++) {
            float a[8], bb[8];
            *reinterpret_cast<float4*>(&a[0])  = *reinterpret_cast<float4*>(Ap + kk * UPAD + tr * 4);
            *reinterpret_cast<float4*>(&a[4])  = *reinterpret_cast<float4*>(Ap + kk * UPAD + 64 + tr * 4);
            *reinterpret_cast<float4*>(&bb[0]) = *reinterpret_cast<float4*>(Bp + kk * UPAD + tc * 4);
            *reinterpret_cast<float4*>(&bb[4]) = *reinterpret_cast<float4*>(Bp + kk * UPAD + 64 + tc * 4);
            #pragma unroll
            for (int u = 0; u < 8; u++)
                #pragma unroll
                for (int v = 0; v < 8; v++)
                    acc[u][v] += a[u] * bb[v];
        }
        if (it + 1 < 32) {
            int q = (it + 1) & 1;
            float* Aq = As + q * 16 * UPAD;
            float* Bq = Bs + q * 16 * UPAD;
            #pragma unroll
            for (int i = 0; i < 2; i++) {
                int kk = kk4 + i * 8;
                *(float4*)&Aq[kk * UPAD + mq] = va[i];
                *(float4*)&Bq[kk * UPAD + mq] = vb[i];
            }
        }
        __syncthreads();
    }

    #pragma unroll
    for (int u = 0; u < 8; u++) {
        int row = bi * 128 + ((u < 4) ? tr * 4 + u : 64 + tr * 4 + (u - 4));
        #pragma unroll
        for (int v = 0; v < 8; v++) {
            int col = bj * 128 + ((v < 4) ? tc * 4 + v : 64 + tc * 4 + (v - 4));
            float o = acc[u][v];
            Wb[(long)row * NN + col] = o;
            if (bi != bj) Wb[(long)col * NN + row] = o;
        }
    }
}

// ---------------- fmean: Fp_b[m] = sum_n T_b[n][m] * u_b[n] ----------------
__global__ void fmean_dot()
{
    int b = blockIdx.y;
    int m = blockIdx.x * 256 + threadIdx.x;
    __shared__ float su[NN];
    const float* Zb = g_Z[b];
    for (int n = threadIdx.x; n < NN; n += 256) su[n] = Zb[(long)n * LDZ + NN];
    __syncthreads();
    float a0 = 0.f, a1 = 0.f, a2 = 0.f, a3 = 0.f;
    #pragma unroll 4
    for (int n = 0; n < NN; n += 4) {
        a0 += Zb[(long)n * LDZ + m]       * su[n];
        a1 += Zb[(long)(n + 1) * LDZ + m] * su[n + 1];
        a2 += Zb[(long)(n + 2) * LDZ + m] * su[n + 2];
        a3 += Zb[(long)(n + 3) * LDZ + m] * su[n + 3];
    }
    g_Fp[b][m] = (a0 + a1) + (a2 + a3);
}

__global__ void fmean_comb(float* __restrict__ out)
{
    int m = blockIdx.x * 256 + threadIdx.x;
    if (m >= NN) return;
    float f0 = g_Fp[0][m], f1 = g_Fp[1][m], f2 = g_Fp[2][m], f3 = g_Fp[3][m];
    #pragma unroll
    for (int q = 0; q < LLt; q++) {
        float v = f0 * g_sm.G[0][q] + f1 * g_sm.G[1][q]
                + f2 * g_sm.G[2][q] + f3 * g_sm.G[3][q];
        out[(long)q * NN + m] = v;
        out[4096L + 2L * 16777216L + (long)m * 4 + q] = v;
    }
}

// ---------------- fvar assembly (sums the two K-half W partials) --------------
__global__ void fvar_kernel(float* __restrict__ out)
{
    int idx = blockIdx.x * 256 + threadIdx.x;
    int a  = idx >> 8;
    int b4 = idx & 255;
    long vi = (long)a * 256 + b4;
    float4 vt = reinterpret_cast<const float4*>(g_Ctt)[vi];
    float4 w0 = reinterpret_cast<const float4*>(g_W[0])[vi];
    float4 w1 = reinterpret_cast<const float4*>(g_W[1])[vi];
    float4 w2 = reinterpret_cast<const float4*>(g_W[2])[vi];
    float4 w3 = reinterpret_cast<const float4*>(g_W[3])[vi];
    float4 x0 = reinterpret_cast<const float4*>(g_W2[0])[vi];
    float4 x1 = reinterpret_cast<const float4*>(g_W2[1])[vi];
    float4 x2 = reinterpret_cast<const float4*>(g_W2[2])[vi];
    float4 x3 = reinterpret_cast<const float4*>(g_W2[3])[vi];
    w0.x += x0.x; w0.y += x0.y; w0.z += x0.z; w0.w += x0.w;
    w1.x += x1.x; w1.y += x1.y; w1.z += x1.z; w1.w += x1.w;
    w2.x += x2.x; w2.y += x2.y; w2.z += x2.z; w2.w += x2.w;
    w3.x += x3.x; w3.y += x3.y; w3.z += x3.z; w3.w += x3.w;
    float4* fv = reinterpret_cast<float4*>(out + 4096);
    #pragma unroll
    for (int q = 0; q < 4; q++) {
        #pragma unroll
        for (int r = 0; r < 4; r++) {
            float cb = g_sm.B[q][r];
            float c0 = g_sm.G[0][q] * g_sm.G[0][r];
            float c1 = g_sm.G[1][q] * g_sm.G[1][r];
            float c2 = g_sm.G[2][q] * g_sm.G[2][r];
            float c3 = g_sm.G[3][q] * g_sm.G[3][r];
            float4 v;
            v.x = cb * vt.x - c0 * w0.x - c1 * w1.x - c2 * w2.x - c3 * w3.x;
            v.y = cb * vt.y - c0 * w0.y - c1 * w1.y - c2 * w2.y - c3 * w3.y;
            v.z = cb * vt.z - c0 * w0.z - c1 * w1.z - c2 * w2.z - c3 * w3.z;
            v.w = cb * vt.w - c0 * w0.w - c1 * w1.w - c2 * w2.w - c3 * w3.w;
            fv[(long)(q * NN + a) * 1024 + r * 256 + b4] = v;
        }
    }
}

// ---------------- noise output (zeros + diagonal in one pass) ----------------
__global__ void noise_fill(float* __restrict__ out)
{
    long i = (long)blockIdx.x * 256 + threadIdx.x;
    long base = i * 4;
    int row = (int)(base >> 12);
    int col0 = (int)(base & 4095);
    float4 v = make_float4(0.f, 0.f, 0.f, 0.f);
    if (row >= col0 && row < col0 + 4)
        reinterpret_cast<float*>(&v)[row - col0] = g_sm.dn[row >> 10];
    reinterpret_cast<float4*>(out + 4096 + 16777216L)[i] = v;
}

// ---------------- launcher (single extra stream; noise & fmean hidden on s2) ----
extern "C" void kernel_launch(void* const* d_in, const int* in_sizes, int n_in,
                              void* d_out, int out_size)
{
    const float* X      = (const float*)d_in[0];
    const float* tX     = (const float*)d_in[1];
    const float* Y      = (const float*)d_in[2];
    const float* lnoise = (const float*)d_in[3];
    const float* cf     = (const float*)d_in[4];
    const float* lvar   = (const float*)d_in[5];
    const float* lls    = (const float*)d_in[6];
    float* out = (float*)d_out;
    int l = in_sizes[3];
    int rank = in_sizes[4] / l;
    (void)l;

    const int DSMEM = (2 * 128 * 129 + 64 * 65 + 128) * 4;   // 149248 B
    const int GSMEM = 2 * 2 * 16 * UPAD * 4;                 // 67584 B
    cudaFuncSetAttribute(diag_step,  cudaFuncAttributeMaxDynamicSharedMemorySize, DSMEM);
    cudaFuncSetAttribute(panel_gemm, cudaFuncAttributeMaxDynamicSharedMemorySize, GSMEM);
    cudaFuncSetAttribute(ustep,      cudaFuncAttributeMaxDynamicSharedMemorySize, GSMEM);
    cudaFuncSetAttribute(syrk_W,     cudaFuncAttributeMaxDynamicSharedMemorySize, GSMEM);

    cudaStream_t s2;
    cudaStreamCreateWithFlags(&s2, cudaStreamNonBlocking);
    cudaEvent_t evA, evB;
    cudaEventCreateWithFlags(&evA, cudaEventDisableTiming);
    cudaEventCreateWithFlags(&evB, cudaEventDisableTiming);

    small_setup<<<1, 32>>>(lnoise, cf, lvar, lls, rank);
    // noise_fill needs only g_sm.dn -> run on s2 hidden under rbf + diag0
    cudaEventRecord(evA, 0);
    cudaStreamWaitEvent(s2, evA, 0);
    noise_fill<<<16384, 256, 0, s2>>>(out);

    rbf_all<<<NN * NN / 256, 256>>>(X, tX, Y);
    diag_step<<<LLt, 256, DSMEM>>>(0);

    // factor + forward-solve sweep; diag(k+1) depends only on panel(k),
    // overlaps the entire ustep(k) on s2.
    for (int k = 0; k < NSTEP; k++) {
        int mrem = NSTEP - 1 - k;
        panel_gemm<<<dim3(mrem + 9, LLt), 256, GSMEM>>>(k);
        if (mrem > 0) {
            cudaEventRecord(evA, 0);
            cudaStreamWaitEvent(s2, evA, 0);
            diag_step<<<LLt, 256, DSMEM, s2>>>(k + 1);               // self-contained
            cudaEventRecord(evB, s2);
            ustep<<<dim3(mrem, mrem + 9, LLt), 256, GSMEM>>>(k);     // skips tile (0,0)
            cudaStreamWaitEvent(0, evB, 0);
        }
    }

    // fmean (needs only final Z) hidden on s2 under syrk on stream0
    cudaEventRecord(evA, 0);
    cudaStreamWaitEvent(s2, evA, 0);
    fmean_dot<<<dim3(4, LLt), 256, 0, s2>>>();
    fmean_comb<<<4, 256, 0, s2>>>(out);
    cudaEventRecord(evB, s2);

    // W_i = T_i^T T_i  (batched syrk, K-split x2: 288 working CTAs)
    syrk_W<<<dim3(8, 8, LLt * 2), 256, GSMEM>>>();

    // join s2, then fvar
    cudaStreamWaitEvent(0, evB, 0);
    fvar_kernel<<<1024, 256>>>(out);
}